// round 1
// baseline (speedup 1.0000x reference)
#include <cuda_runtime.h>

#define NN 50000
#define NE 800000
#define ET (NE + NN)
#define H 128

// ---------------- scratch (static __device__, no allocation) ----------------
__device__ float g_h[NN * H];       // current activations
__device__ float g_lin[NN * H];     // per-layer linear output h = in @ W^T
__device__ float g_agg[NN * H];     // segment-sum aggregation output
__device__ float g_ssrc[NN * 4];    // per-node attention scalars (src side)
__device__ float g_sdst[NN * 4];    // per-node attention scalars (dst side)
__device__ unsigned g_m[NN * 4];    // segment max (ordered-uint encoded)
__device__ float g_den[NN * 4];     // softmax denominators
__device__ float g_e[ET * 4];       // per-edge logits, then exp values
__device__ float g_sum[H];          // BN channel sums
__device__ float g_sum2[H];         // BN channel sum of squares
__device__ float g_hid[NN * 64];    // MLP hidden

// ---------------- helpers ----------------
__device__ __forceinline__ unsigned fenc(float f) {
    unsigned u = __float_as_uint(f);
    return (u & 0x80000000u) ? ~u : (u | 0x80000000u);
}
__device__ __forceinline__ float fdec(unsigned u) {
    return (u & 0x80000000u) ? __uint_as_float(u & 0x7FFFFFFFu)
                             : __uint_as_float(~u);
}
#define ENC_NEG_INF 0x007FFFFFu  // fenc(-inf)

// ---------------- input layer: h = relu(x @ W_in^T + b_in), F_IN=5 ----------------
__global__ void k_input(const float* __restrict__ x, const float* __restrict__ W,
                        const float* __restrict__ b) {
    __shared__ float sW[H * 5];
    __shared__ float sb[H];
    for (int i = threadIdx.x; i < H * 5; i += blockDim.x) sW[i] = W[i];
    for (int i = threadIdx.x; i < H; i += blockDim.x) sb[i] = b[i];
    __syncthreads();
    int total = NN * H;
    for (int idx = blockIdx.x * blockDim.x + threadIdx.x; idx < total;
         idx += gridDim.x * blockDim.x) {
        int n = idx >> 7, c = idx & 127;
        const float* xr = x + n * 5;
        float acc = sb[c];
#pragma unroll
        for (int k = 0; k < 5; k++) acc = fmaf(xr[k], sW[c * 5 + k], acc);
        g_h[idx] = fmaxf(acc, 0.f);
    }
}

// ---------------- GAT GEMM: g_lin = g_h @ W^T, fused s_src/s_dst epilogue ----------------
// blockDim = 128. Each thread owns one output channel; 8 nodes per iteration.
template <int HEADS>
__global__ void k_gemm_gat(const float* __restrict__ W,
                           const float* __restrict__ a_s,
                           const float* __restrict__ a_d) {
    extern __shared__ float smem[];
    float* sW = smem;              // 128 * 129
    float* sx = smem + 128 * 129;  // 128 k-positions * 8 nodes
    __shared__ float sRed[2][4][8];

    const int tid = threadIdx.x;
    for (int idx = tid; idx < 128 * 128; idx += 128) {
        int t = idx >> 7, k = idx & 127;
        sW[t * 129 + k] = W[idx];  // coalesced read, padded store
    }
    const float sa = a_s[tid];
    const float sd = a_d[tid];
    __syncthreads();

    const int NCH = NN / 8;  // 6250, exact
    for (int chunk = blockIdx.x; chunk < NCH; chunk += gridDim.x) {
        const int n0 = chunk * 8;
        __syncthreads();  // protect sx/sRed from previous iteration
#pragma unroll
        for (int nb = 0; nb < 8; nb++) sx[tid * 8 + nb] = g_h[(n0 + nb) * 128 + tid];
        __syncthreads();

        float acc[8];
#pragma unroll
        for (int i = 0; i < 8; i++) acc[i] = 0.f;
#pragma unroll 4
        for (int k = 0; k < 128; k++) {
            float w = sW[tid * 129 + k];
            float4 xa = *reinterpret_cast<float4*>(&sx[k * 8]);
            float4 xb = *reinterpret_cast<float4*>(&sx[k * 8 + 4]);
            acc[0] = fmaf(w, xa.x, acc[0]);
            acc[1] = fmaf(w, xa.y, acc[1]);
            acc[2] = fmaf(w, xa.z, acc[2]);
            acc[3] = fmaf(w, xa.w, acc[3]);
            acc[4] = fmaf(w, xb.x, acc[4]);
            acc[5] = fmaf(w, xb.y, acc[5]);
            acc[6] = fmaf(w, xb.z, acc[6]);
            acc[7] = fmaf(w, xb.w, acc[7]);
        }
#pragma unroll
        for (int nb = 0; nb < 8; nb++) g_lin[(n0 + nb) * 128 + tid] = acc[nb];

        const int lane = tid & 31, wrp = tid >> 5;
#pragma unroll
        for (int nb = 0; nb < 8; nb++) {
            float vs = acc[nb] * sa, vd = acc[nb] * sd;
#pragma unroll
            for (int o = 16; o > 0; o >>= 1) {
                vs += __shfl_xor_sync(0xffffffffu, vs, o);
                vd += __shfl_xor_sync(0xffffffffu, vd, o);
            }
            if (HEADS == 4) {
                if (lane == 0) {
                    g_ssrc[(n0 + nb) * 4 + wrp] = vs;
                    g_sdst[(n0 + nb) * 4 + wrp] = vd;
                }
            } else {
                if (lane == 0) {
                    sRed[0][wrp][nb] = vs;
                    sRed[1][wrp][nb] = vd;
                }
            }
        }
        if (HEADS == 1) {
            __syncthreads();
            if (tid < 8) {
                float vs = 0.f, vd = 0.f;
#pragma unroll
                for (int w2 = 0; w2 < 4; w2++) {
                    vs += sRed[0][w2][tid];
                    vd += sRed[1][w2][tid];
                }
                g_ssrc[n0 + tid] = vs;
                g_sdst[n0 + tid] = vd;
            }
        }
    }
}

// ---------------- per-layer init: agg=0, m=-inf, den=0, bn sums=0 ----------------
__global__ void k_init(int heads) {
    const int total = NN * H;
    const int nm = NN * heads;
    for (int idx = blockIdx.x * blockDim.x + threadIdx.x; idx < total;
         idx += gridDim.x * blockDim.x) {
        g_agg[idx] = 0.f;
        if (idx < nm) {
            g_m[idx] = ENC_NEG_INF;
            g_den[idx] = 0.f;
        }
        if (idx < H) {
            g_sum[idx] = 0.f;
            g_sum2[idx] = 0.f;
        }
    }
}

// ---------------- edge pass 1: logit + segment max ----------------
template <int HEADS>
__global__ void k_edge1(const int* __restrict__ ei) {
    int e = blockIdx.x * blockDim.x + threadIdx.x;
    if (e >= ET) return;
    int s, d;
    if (e < NE) { s = ei[e]; d = ei[NE + e]; } else { s = d = e - NE; }
    if (HEADS == 4) {
        float4 vs = *reinterpret_cast<const float4*>(&g_ssrc[s * 4]);
        float4 vd = *reinterpret_cast<const float4*>(&g_sdst[d * 4]);
        float4 l;
        l.x = vs.x + vd.x; l.x = l.x > 0.f ? l.x : 0.2f * l.x;
        l.y = vs.y + vd.y; l.y = l.y > 0.f ? l.y : 0.2f * l.y;
        l.z = vs.z + vd.z; l.z = l.z > 0.f ? l.z : 0.2f * l.z;
        l.w = vs.w + vd.w; l.w = l.w > 0.f ? l.w : 0.2f * l.w;
        *reinterpret_cast<float4*>(&g_e[e * 4]) = l;
        atomicMax(&g_m[d * 4 + 0], fenc(l.x));
        atomicMax(&g_m[d * 4 + 1], fenc(l.y));
        atomicMax(&g_m[d * 4 + 2], fenc(l.z));
        atomicMax(&g_m[d * 4 + 3], fenc(l.w));
    } else {
        float l = g_ssrc[s] + g_sdst[d];
        l = l > 0.f ? l : 0.2f * l;
        g_e[e] = l;
        atomicMax(&g_m[d], fenc(l));
    }
}

// ---------------- edge pass 2: e = exp(logit - m[dst]); denom += e ----------------
template <int HEADS>
__global__ void k_edge2(const int* __restrict__ ei) {
    int e = blockIdx.x * blockDim.x + threadIdx.x;
    if (e >= ET) return;
    int d = (e < NE) ? ei[NE + e] : e - NE;
    if (HEADS == 4) {
        float4 l = *reinterpret_cast<const float4*>(&g_e[e * 4]);
        uint4 mu = *reinterpret_cast<const uint4*>(&g_m[d * 4]);
        float4 ev;
        ev.x = expf(l.x - fdec(mu.x));
        ev.y = expf(l.y - fdec(mu.y));
        ev.z = expf(l.z - fdec(mu.z));
        ev.w = expf(l.w - fdec(mu.w));
        *reinterpret_cast<float4*>(&g_e[e * 4]) = ev;
        atomicAdd(&g_den[d * 4 + 0], ev.x);
        atomicAdd(&g_den[d * 4 + 1], ev.y);
        atomicAdd(&g_den[d * 4 + 2], ev.z);
        atomicAdd(&g_den[d * 4 + 3], ev.w);
    } else {
        float ev = expf(g_e[e] - fdec(g_m[d]));
        g_e[e] = ev;
        atomicAdd(&g_den[d], ev);
    }
}

// ---------------- edge pass 3: agg[dst] += h[src] * alpha (warp per edge) ----------------
template <int HEADS>
__global__ void k_edge3(const int* __restrict__ ei) {
    int e = (blockIdx.x * blockDim.x + threadIdx.x) >> 5;
    int lane = threadIdx.x & 31;
    if (e >= ET) return;
    int s, d;
    if (e < NE) { s = ei[e]; d = ei[NE + e]; } else { s = d = e - NE; }
    float alpha;
    if (HEADS == 4) {
        float4 ev = *reinterpret_cast<const float4*>(&g_e[e * 4]);
        float4 dn = *reinterpret_cast<const float4*>(&g_den[d * 4]);
        int hd = lane >> 3;  // lane handles channels 4*lane..4*lane+3 -> head = lane/8
        float evh = (hd == 0) ? ev.x : (hd == 1) ? ev.y : (hd == 2) ? ev.z : ev.w;
        float dnh = (hd == 0) ? dn.x : (hd == 1) ? dn.y : (hd == 2) ? dn.z : dn.w;
        alpha = evh / (dnh + 1e-16f);
    } else {
        alpha = g_e[e] / (g_den[d] + 1e-16f);
    }
    float4 hv = *reinterpret_cast<const float4*>(&g_lin[s * 128 + lane * 4]);
    float4 v;
    v.x = hv.x * alpha; v.y = hv.y * alpha; v.z = hv.z * alpha; v.w = hv.w * alpha;
    float* p = &g_agg[d * 128 + lane * 4];
    asm volatile("red.global.add.v4.f32 [%0], {%1,%2,%3,%4};"
                 :: "l"(p), "f"(v.x), "f"(v.y), "f"(v.z), "f"(v.w)
                 : "memory");
}

// ---------------- BN stats: per-channel sum / sumsq ----------------
__global__ void k_bnstats() {
    int c = threadIdx.x;  // blockDim = 128
    float s = 0.f, s2 = 0.f;
    for (int n = blockIdx.x; n < NN; n += gridDim.x) {
        float v = g_agg[n * 128 + c];
        s += v;
        s2 = fmaf(v, v, s2);
    }
    atomicAdd(&g_sum[c], s);
    atomicAdd(&g_sum2[c], s2);
}

// ---------------- BN apply (+optional relu): g_h = bn(g_agg) ----------------
__global__ void k_bnapply(const float* __restrict__ gam, const float* __restrict__ bet,
                          int do_relu) {
    __shared__ float sc[H], sh[H];
    if (threadIdx.x < H) {
        int c = threadIdx.x;
        float mu = g_sum[c] * (1.f / NN);
        float var = g_sum2[c] * (1.f / NN) - mu * mu;
        float scale = gam[c] * rsqrtf(var + 1e-5f);
        sc[c] = scale;
        sh[c] = bet[c] - mu * scale;
    }
    __syncthreads();
    const int total = NN * H;
    for (int idx = blockIdx.x * blockDim.x + threadIdx.x; idx < total;
         idx += gridDim.x * blockDim.x) {
        int c = idx & 127;
        float v = fmaf(g_agg[idx], sc[c], sh[c]);
        g_h[idx] = do_relu ? fmaxf(v, 0.f) : v;
    }
}

// ---------------- MLP layer 1: hid = relu(g_h @ Wc1^T + bc1), OUT=64 ----------------
__global__ void k_mlp1(const float* __restrict__ W, const float* __restrict__ b) {
    __shared__ float sW[64 * 129];
    __shared__ float sx[128 * 8];
    const int tid = threadIdx.x;  // 64
    for (int idx = tid; idx < 64 * 128; idx += 64) {
        int t = idx >> 7, k = idx & 127;
        sW[t * 129 + k] = W[idx];
    }
    const float bias = b[tid];
    __syncthreads();
    const int NCH = NN / 8;
    for (int chunk = blockIdx.x; chunk < NCH; chunk += gridDim.x) {
        const int n0 = chunk * 8;
        __syncthreads();
#pragma unroll
        for (int nb = 0; nb < 8; nb++)
            for (int k = tid; k < 128; k += 64) sx[k * 8 + nb] = g_h[(n0 + nb) * 128 + k];
        __syncthreads();
        float acc[8];
#pragma unroll
        for (int i = 0; i < 8; i++) acc[i] = 0.f;
#pragma unroll 4
        for (int k = 0; k < 128; k++) {
            float w = sW[tid * 129 + k];
            float4 xa = *reinterpret_cast<float4*>(&sx[k * 8]);
            float4 xb = *reinterpret_cast<float4*>(&sx[k * 8 + 4]);
            acc[0] = fmaf(w, xa.x, acc[0]);
            acc[1] = fmaf(w, xa.y, acc[1]);
            acc[2] = fmaf(w, xa.z, acc[2]);
            acc[3] = fmaf(w, xa.w, acc[3]);
            acc[4] = fmaf(w, xb.x, acc[4]);
            acc[5] = fmaf(w, xb.y, acc[5]);
            acc[6] = fmaf(w, xb.z, acc[6]);
            acc[7] = fmaf(w, xb.w, acc[7]);
        }
#pragma unroll
        for (int nb = 0; nb < 8; nb++)
            g_hid[(n0 + nb) * 64 + tid] = fmaxf(acc[nb] + bias, 0.f);
    }
}

// ---------------- MLP layer 2: out[n] = hid[n] . Wc2 + bc2 (warp per node) ----------------
__global__ void k_mlp2(const float* __restrict__ W, const float* __restrict__ b,
                       float* __restrict__ out) {
    __shared__ float sW[64];
    if (threadIdx.x < 64) sW[threadIdx.x] = W[threadIdx.x];
    __syncthreads();
    int n = (blockIdx.x * blockDim.x + threadIdx.x) >> 5;
    int lane = threadIdx.x & 31;
    if (n >= NN) return;
    float2 hv = *reinterpret_cast<const float2*>(&g_hid[n * 64 + lane * 2]);
    float acc = hv.x * sW[lane * 2] + hv.y * sW[lane * 2 + 1];
#pragma unroll
    for (int o = 16; o > 0; o >>= 1) acc += __shfl_xor_sync(0xffffffffu, acc, o);
    if (lane == 0) out[n] = acc + b[0];
}

// ---------------- launch ----------------
extern "C" void kernel_launch(void* const* d_in, const int* in_sizes, int n_in,
                              void* d_out, int out_size) {
    const float* x    = (const float*)d_in[0];
    const int*   ei   = (const int*)d_in[1];
    const float* W_in = (const float*)d_in[2];
    const float* b_in = (const float*)d_in[3];
    const float* Wl[3]  = {(const float*)d_in[4], (const float*)d_in[8], (const float*)d_in[12]};
    const float* ASl[3] = {(const float*)d_in[5], (const float*)d_in[9], (const float*)d_in[13]};
    const float* ADl[3] = {(const float*)d_in[6], (const float*)d_in[10], (const float*)d_in[14]};
    // biases b0/b1/b2 (d_in[7,11,15]) are mathematically cancelled by BatchNorm
    const float* Gl[3]  = {(const float*)d_in[16], (const float*)d_in[18], (const float*)d_in[20]};
    const float* Bl[3]  = {(const float*)d_in[17], (const float*)d_in[19], (const float*)d_in[21]};
    const float* Wc1 = (const float*)d_in[22];
    const float* bc1 = (const float*)d_in[23];
    const float* Wc2 = (const float*)d_in[24];
    const float* bc2 = (const float*)d_in[25];
    float* out = (float*)d_out;

    const int GEMM_SMEM = (128 * 129 + 128 * 8) * sizeof(float);  // 70144
    cudaFuncSetAttribute(k_gemm_gat<4>, cudaFuncAttributeMaxDynamicSharedMemorySize, GEMM_SMEM);
    cudaFuncSetAttribute(k_gemm_gat<1>, cudaFuncAttributeMaxDynamicSharedMemorySize, GEMM_SMEM);

    const int EB = 256;
    const int EG12 = (ET + EB - 1) / EB;        // thread per edge
    const int EG3  = (ET * 32 + EB - 1) / EB;   // warp per edge

    k_input<<<1024, 256>>>(x, W_in, b_in);

    for (int l = 0; l < 3; l++) {
        if (l < 2) {
            k_gemm_gat<4><<<444, 128, GEMM_SMEM>>>(Wl[l], ASl[l], ADl[l]);
            k_init<<<4096, 256>>>(4);
            k_edge1<4><<<EG12, EB>>>(ei);
            k_edge2<4><<<EG12, EB>>>(ei);
            k_edge3<4><<<EG3, EB>>>(ei);
        } else {
            k_gemm_gat<1><<<444, 128, GEMM_SMEM>>>(Wl[l], ASl[l], ADl[l]);
            k_init<<<4096, 256>>>(1);
            k_edge1<1><<<EG12, EB>>>(ei);
            k_edge2<1><<<EG12, EB>>>(ei);
            k_edge3<1><<<EG3, EB>>>(ei);
        }
        k_bnstats<<<512, 128>>>();
        k_bnapply<<<2048, 256>>>(Gl[l], Bl[l], (l < 2) ? 1 : 0);
    }

    k_mlp1<<<1024, 64>>>(Wc1, bc1);
    k_mlp2<<<(NN * 32 + EB - 1) / EB, EB>>>(Wc2, bc2, out);
}

// round 2
// speedup vs baseline: 1.2097x; 1.2097x over previous
#include <cuda_runtime.h>

#define NN 50000
#define NE 800000
#define ET (NE + NN)
#define H 128

// ---------------- scratch (static __device__, no allocation) ----------------
__device__ float g_h[NN * H];       // current activations
__device__ float g_lin[NN * H];     // per-layer linear output h = in @ W^T
__device__ float g_agg[NN * H];     // segment aggregation output
__device__ float g_ssrc[NN * 4];    // per-node attention scalars (src side)
__device__ float g_sdst[NN * 4];    // per-node attention scalars (dst side)
__device__ float g_sum[H];          // BN channel sums
__device__ float g_sum2[H];         // BN channel sum of squares
__device__ float g_hid[NN * 64];    // MLP hidden
// CSR (built once per call; shared by the 3 GAT layers)
__device__ int g_cnt[NN];
__device__ int g_rowptr[NN + 1];
__device__ int g_woff[NN];
__device__ int g_csrc[ET];

// ---------------- input layer: h = relu(x @ W_in^T + b_in), F_IN=5 ----------------
__global__ void k_input(const float* __restrict__ x, const float* __restrict__ W,
                        const float* __restrict__ b) {
    __shared__ float sW[H * 5];
    __shared__ float sb[H];
    for (int i = threadIdx.x; i < H * 5; i += blockDim.x) sW[i] = W[i];
    for (int i = threadIdx.x; i < H; i += blockDim.x) sb[i] = b[i];
    __syncthreads();
    int total = NN * H;
    for (int idx = blockIdx.x * blockDim.x + threadIdx.x; idx < total;
         idx += gridDim.x * blockDim.x) {
        int n = idx >> 7, c = idx & 127;
        const float* xr = x + n * 5;
        float acc = sb[c];
#pragma unroll
        for (int k = 0; k < 5; k++) acc = fmaf(xr[k], sW[c * 5 + k], acc);
        g_h[idx] = fmaxf(acc, 0.f);
    }
}

// ---------------- CSR build ----------------
__global__ void k_zero_cnt() {
    for (int i = blockIdx.x * blockDim.x + threadIdx.x; i < NN;
         i += gridDim.x * blockDim.x)
        g_cnt[i] = 0;
}

__global__ void k_hist(const int* __restrict__ ei) {
    int e = blockIdx.x * blockDim.x + threadIdx.x;
    if (e >= ET) return;
    int d = (e < NE) ? ei[NE + e] : e - NE;
    atomicAdd(&g_cnt[d], 1);
}

__global__ void k_scan() {  // single block, 1024 threads
    __shared__ int sp[1024];
    const int C = (NN + 1023) / 1024;  // 49
    int t = threadIdx.x;
    int b = t * C;
    int sum = 0;
    for (int i = 0; i < C; i++) {
        int idx = b + i;
        if (idx < NN) sum += g_cnt[idx];
    }
    sp[t] = sum;
    __syncthreads();
    for (int off = 1; off < 1024; off <<= 1) {
        int v = (t >= off) ? sp[t - off] : 0;
        __syncthreads();
        sp[t] += v;
        __syncthreads();
    }
    int run = (t == 0) ? 0 : sp[t - 1];
    for (int i = 0; i < C; i++) {
        int idx = b + i;
        if (idx < NN) {
            g_rowptr[idx] = run;
            g_woff[idx] = run;
            run += g_cnt[idx];
        }
    }
    if (t == 1023) g_rowptr[NN] = run;
}

__global__ void k_scatter(const int* __restrict__ ei) {
    int e = blockIdx.x * blockDim.x + threadIdx.x;
    if (e >= ET) return;
    int s, d;
    if (e < NE) { s = ei[e]; d = ei[NE + e]; } else { s = d = e - NE; }
    int pos = atomicAdd(&g_woff[d], 1);
    g_csrc[pos] = s;
}

// ---------------- GAT GEMM: g_lin = g_h @ W^T, fused s_src/s_dst epilogue ----------------
template <int HEADS>
__global__ void k_gemm_gat(const float* __restrict__ W,
                           const float* __restrict__ a_s,
                           const float* __restrict__ a_d) {
    extern __shared__ float smem[];
    float* sW = smem;              // 128 * 129
    float* sx = smem + 128 * 129;  // 128 k-positions * 8 nodes
    __shared__ float sRed[2][4][8];

    const int tid = threadIdx.x;
    for (int idx = tid; idx < 128 * 128; idx += 128) {
        int t = idx >> 7, k = idx & 127;
        sW[t * 129 + k] = W[idx];
    }
    const float sa = a_s[tid];
    const float sd = a_d[tid];
    __syncthreads();

    const int NCH = NN / 8;  // 6250, exact
    for (int chunk = blockIdx.x; chunk < NCH; chunk += gridDim.x) {
        const int n0 = chunk * 8;
        __syncthreads();
#pragma unroll
        for (int nb = 0; nb < 8; nb++) sx[tid * 8 + nb] = g_h[(n0 + nb) * 128 + tid];
        __syncthreads();

        float acc[8];
#pragma unroll
        for (int i = 0; i < 8; i++) acc[i] = 0.f;
#pragma unroll 4
        for (int k = 0; k < 128; k++) {
            float w = sW[tid * 129 + k];
            float4 xa = *reinterpret_cast<float4*>(&sx[k * 8]);
            float4 xb = *reinterpret_cast<float4*>(&sx[k * 8 + 4]);
            acc[0] = fmaf(w, xa.x, acc[0]);
            acc[1] = fmaf(w, xa.y, acc[1]);
            acc[2] = fmaf(w, xa.z, acc[2]);
            acc[3] = fmaf(w, xa.w, acc[3]);
            acc[4] = fmaf(w, xb.x, acc[4]);
            acc[5] = fmaf(w, xb.y, acc[5]);
            acc[6] = fmaf(w, xb.z, acc[6]);
            acc[7] = fmaf(w, xb.w, acc[7]);
        }
#pragma unroll
        for (int nb = 0; nb < 8; nb++) g_lin[(n0 + nb) * 128 + tid] = acc[nb];

        const int lane = tid & 31, wrp = tid >> 5;
#pragma unroll
        for (int nb = 0; nb < 8; nb++) {
            float vs = acc[nb] * sa, vd = acc[nb] * sd;
#pragma unroll
            for (int o = 16; o > 0; o >>= 1) {
                vs += __shfl_xor_sync(0xffffffffu, vs, o);
                vd += __shfl_xor_sync(0xffffffffu, vd, o);
            }
            if (HEADS == 4) {
                if (lane == 0) {
                    g_ssrc[(n0 + nb) * 4 + wrp] = vs;
                    g_sdst[(n0 + nb) * 4 + wrp] = vd;
                }
            } else {
                if (lane == 0) {
                    sRed[0][wrp][nb] = vs;
                    sRed[1][wrp][nb] = vd;
                }
            }
        }
        if (HEADS == 1) {
            __syncthreads();
            if (tid < 8) {
                float vs = 0.f, vd = 0.f;
#pragma unroll
                for (int w2 = 0; w2 < 4; w2++) {
                    vs += sRed[0][w2][tid];
                    vd += sRed[1][w2][tid];
                }
                g_ssrc[n0 + tid] = vs;
                g_sdst[n0 + tid] = vd;
            }
        }
    }
}

// ---------------- fused attention + aggregation: warp per destination node ----------------
// agg[d] = sum_e exp(l_e - m) * h_lin[src_e] / sum_e exp(l_e - m)
template <int HEADS>
__global__ void k_attnagg() {
    const int w = (blockIdx.x * blockDim.x + threadIdx.x) >> 5;
    const int lane = threadIdx.x & 31;
    if (w >= NN) return;
    const int beg = g_rowptr[w];
    const int end = g_rowptr[w + 1];

    float4 sd;
    if (HEADS == 4) sd = *reinterpret_cast<const float4*>(&g_sdst[w * 4]);
    else sd.x = g_sdst[w];

    // pass 1: per-head max over the row
    float4 mx = make_float4(-1e30f, -1e30f, -1e30f, -1e30f);
    for (int i = beg + lane; i < end; i += 32) {
        int s = g_csrc[i];
        if (HEADS == 4) {
            float4 vs = *reinterpret_cast<const float4*>(&g_ssrc[s * 4]);
            float lx = vs.x + sd.x; lx = lx > 0.f ? lx : 0.2f * lx;
            float ly = vs.y + sd.y; ly = ly > 0.f ? ly : 0.2f * ly;
            float lz = vs.z + sd.z; lz = lz > 0.f ? lz : 0.2f * lz;
            float lw = vs.w + sd.w; lw = lw > 0.f ? lw : 0.2f * lw;
            mx.x = fmaxf(mx.x, lx); mx.y = fmaxf(mx.y, ly);
            mx.z = fmaxf(mx.z, lz); mx.w = fmaxf(mx.w, lw);
        } else {
            float l = g_ssrc[s] + sd.x;
            l = l > 0.f ? l : 0.2f * l;
            mx.x = fmaxf(mx.x, l);
        }
    }
#pragma unroll
    for (int o = 16; o > 0; o >>= 1) {
        mx.x = fmaxf(mx.x, __shfl_xor_sync(0xffffffffu, mx.x, o));
        if (HEADS == 4) {
            mx.y = fmaxf(mx.y, __shfl_xor_sync(0xffffffffu, mx.y, o));
            mx.z = fmaxf(mx.z, __shfl_xor_sync(0xffffffffu, mx.z, o));
            mx.w = fmaxf(mx.w, __shfl_xor_sync(0xffffffffu, mx.w, o));
        }
    }

    // pass 2: e = exp(l - m); acc += e * h_lin[src]; D += e
    const int hd = lane >> 3;  // head for this lane's 4 channels (HEADS==4)
    float4 sume = make_float4(0.f, 0.f, 0.f, 0.f);
    float4 acc = make_float4(0.f, 0.f, 0.f, 0.f);
    for (int base = beg; base < end; base += 32) {
        const int i = base + lane;
        int s = 0;
        float4 ev = make_float4(0.f, 0.f, 0.f, 0.f);
        if (i < end) {
            s = g_csrc[i];
            if (HEADS == 4) {
                float4 vs = *reinterpret_cast<const float4*>(&g_ssrc[s * 4]);
                float lx = vs.x + sd.x; lx = lx > 0.f ? lx : 0.2f * lx;
                float ly = vs.y + sd.y; ly = ly > 0.f ? ly : 0.2f * ly;
                float lz = vs.z + sd.z; lz = lz > 0.f ? lz : 0.2f * lz;
                float lw = vs.w + sd.w; lw = lw > 0.f ? lw : 0.2f * lw;
                ev.x = __expf(lx - mx.x); ev.y = __expf(ly - mx.y);
                ev.z = __expf(lz - mx.z); ev.w = __expf(lw - mx.w);
                sume.x += ev.x; sume.y += ev.y; sume.z += ev.z; sume.w += ev.w;
            } else {
                float l = g_ssrc[s] + sd.x;
                l = l > 0.f ? l : 0.2f * l;
                ev.x = __expf(l - mx.x);
                sume.x += ev.x;
            }
        }
        const int cnt = min(32, end - base);
        for (int j = 0; j < cnt; j++) {
            int sj = __shfl_sync(0xffffffffu, s, j);
            float evh;
            if (HEADS == 4) {
                float e0 = __shfl_sync(0xffffffffu, ev.x, j);
                float e1 = __shfl_sync(0xffffffffu, ev.y, j);
                float e2 = __shfl_sync(0xffffffffu, ev.z, j);
                float e3 = __shfl_sync(0xffffffffu, ev.w, j);
                evh = (hd == 0) ? e0 : (hd == 1) ? e1 : (hd == 2) ? e2 : e3;
            } else {
                evh = __shfl_sync(0xffffffffu, ev.x, j);
            }
            float4 hv = *reinterpret_cast<const float4*>(&g_lin[sj * 128 + lane * 4]);
            acc.x = fmaf(evh, hv.x, acc.x);
            acc.y = fmaf(evh, hv.y, acc.y);
            acc.z = fmaf(evh, hv.z, acc.z);
            acc.w = fmaf(evh, hv.w, acc.w);
        }
    }
    // reduce denominators across warp
#pragma unroll
    for (int o = 16; o > 0; o >>= 1) {
        sume.x += __shfl_xor_sync(0xffffffffu, sume.x, o);
        if (HEADS == 4) {
            sume.y += __shfl_xor_sync(0xffffffffu, sume.y, o);
            sume.z += __shfl_xor_sync(0xffffffffu, sume.z, o);
            sume.w += __shfl_xor_sync(0xffffffffu, sume.w, o);
        }
    }
    float dh;
    if (HEADS == 4)
        dh = (hd == 0) ? sume.x : (hd == 1) ? sume.y : (hd == 2) ? sume.z : sume.w;
    else
        dh = sume.x;
    float inv = 1.f / (dh + 1e-16f);
    acc.x *= inv; acc.y *= inv; acc.z *= inv; acc.w *= inv;
    *reinterpret_cast<float4*>(&g_agg[w * 128 + lane * 4]) = acc;
}

// ---------------- BN ----------------
__global__ void k_zero_bn() {
    if (threadIdx.x < H) {
        g_sum[threadIdx.x] = 0.f;
        g_sum2[threadIdx.x] = 0.f;
    }
}

__global__ void k_bnstats() {
    int c = threadIdx.x;  // blockDim = 128
    float s = 0.f, s2 = 0.f;
    for (int n = blockIdx.x; n < NN; n += gridDim.x) {
        float v = g_agg[n * 128 + c];
        s += v;
        s2 = fmaf(v, v, s2);
    }
    atomicAdd(&g_sum[c], s);
    atomicAdd(&g_sum2[c], s2);
}

__global__ void k_bnapply(const float* __restrict__ gam, const float* __restrict__ bet,
                          int do_relu) {
    __shared__ float sc[H], sh[H];
    if (threadIdx.x < H) {
        int c = threadIdx.x;
        float mu = g_sum[c] * (1.f / NN);
        float var = g_sum2[c] * (1.f / NN) - mu * mu;
        float scale = gam[c] * rsqrtf(var + 1e-5f);
        sc[c] = scale;
        sh[c] = bet[c] - mu * scale;
    }
    __syncthreads();
    const int total = NN * H;
    for (int idx = blockIdx.x * blockDim.x + threadIdx.x; idx < total;
         idx += gridDim.x * blockDim.x) {
        int c = idx & 127;
        float v = fmaf(g_agg[idx], sc[c], sh[c]);
        g_h[idx] = do_relu ? fmaxf(v, 0.f) : v;
    }
}

// ---------------- MLP layer 1: hid = relu(g_h @ Wc1^T + bc1), OUT=64 ----------------
__global__ void k_mlp1(const float* __restrict__ W, const float* __restrict__ b) {
    __shared__ float sW[64 * 129];
    __shared__ float sx[128 * 8];
    const int tid = threadIdx.x;  // 64
    for (int idx = tid; idx < 64 * 128; idx += 64) {
        int t = idx >> 7, k = idx & 127;
        sW[t * 129 + k] = W[idx];
    }
    const float bias = b[tid];
    __syncthreads();
    const int NCH = NN / 8;
    for (int chunk = blockIdx.x; chunk < NCH; chunk += gridDim.x) {
        const int n0 = chunk * 8;
        __syncthreads();
#pragma unroll
        for (int nb = 0; nb < 8; nb++)
            for (int k = tid; k < 128; k += 64) sx[k * 8 + nb] = g_h[(n0 + nb) * 128 + k];
        __syncthreads();
        float acc[8];
#pragma unroll
        for (int i = 0; i < 8; i++) acc[i] = 0.f;
#pragma unroll 4
        for (int k = 0; k < 128; k++) {
            float w = sW[tid * 129 + k];
            float4 xa = *reinterpret_cast<float4*>(&sx[k * 8]);
            float4 xb = *reinterpret_cast<float4*>(&sx[k * 8 + 4]);
            acc[0] = fmaf(w, xa.x, acc[0]);
            acc[1] = fmaf(w, xa.y, acc[1]);
            acc[2] = fmaf(w, xa.z, acc[2]);
            acc[3] = fmaf(w, xa.w, acc[3]);
            acc[4] = fmaf(w, xb.x, acc[4]);
            acc[5] = fmaf(w, xb.y, acc[5]);
            acc[6] = fmaf(w, xb.z, acc[6]);
            acc[7] = fmaf(w, xb.w, acc[7]);
        }
#pragma unroll
        for (int nb = 0; nb < 8; nb++)
            g_hid[(n0 + nb) * 64 + tid] = fmaxf(acc[nb] + bias, 0.f);
    }
}

// ---------------- MLP layer 2: out[n] = hid[n] . Wc2 + bc2 (warp per node) ----------------
__global__ void k_mlp2(const float* __restrict__ W, const float* __restrict__ b,
                       float* __restrict__ out) {
    __shared__ float sW[64];
    if (threadIdx.x < 64) sW[threadIdx.x] = W[threadIdx.x];
    __syncthreads();
    int n = (blockIdx.x * blockDim.x + threadIdx.x) >> 5;
    int lane = threadIdx.x & 31;
    if (n >= NN) return;
    float2 hv = *reinterpret_cast<const float2*>(&g_hid[n * 64 + lane * 2]);
    float acc = hv.x * sW[lane * 2] + hv.y * sW[lane * 2 + 1];
#pragma unroll
    for (int o = 16; o > 0; o >>= 1) acc += __shfl_xor_sync(0xffffffffu, acc, o);
    if (lane == 0) out[n] = acc + b[0];
}

// ---------------- launch ----------------
extern "C" void kernel_launch(void* const* d_in, const int* in_sizes, int n_in,
                              void* d_out, int out_size) {
    const float* x    = (const float*)d_in[0];
    const int*   ei   = (const int*)d_in[1];
    const float* W_in = (const float*)d_in[2];
    const float* b_in = (const float*)d_in[3];
    const float* Wl[3]  = {(const float*)d_in[4], (const float*)d_in[8], (const float*)d_in[12]};
    const float* ASl[3] = {(const float*)d_in[5], (const float*)d_in[9], (const float*)d_in[13]};
    const float* ADl[3] = {(const float*)d_in[6], (const float*)d_in[10], (const float*)d_in[14]};
    // GAT biases b0/b1/b2 are cancelled exactly by the following BatchNorm
    const float* Gl[3]  = {(const float*)d_in[16], (const float*)d_in[18], (const float*)d_in[20]};
    const float* Bl[3]  = {(const float*)d_in[17], (const float*)d_in[19], (const float*)d_in[21]};
    const float* Wc1 = (const float*)d_in[22];
    const float* bc1 = (const float*)d_in[23];
    const float* Wc2 = (const float*)d_in[24];
    const float* bc2 = (const float*)d_in[25];
    float* out = (float*)d_out;

    const int GEMM_SMEM = (128 * 129 + 128 * 8) * sizeof(float);  // 70144
    cudaFuncSetAttribute(k_gemm_gat<4>, cudaFuncAttributeMaxDynamicSharedMemorySize, GEMM_SMEM);
    cudaFuncSetAttribute(k_gemm_gat<1>, cudaFuncAttributeMaxDynamicSharedMemorySize, GEMM_SMEM);

    const int EB = 256;
    const int EG = (ET + EB - 1) / EB;
    const int AGG_BLOCKS = (NN * 32 + EB - 1) / EB;  // warp per node

    // CSR build (once; reused by all 3 layers) — overlaps nothing, but cheap
    k_zero_cnt<<<64, 1024>>>();
    k_hist<<<EG, EB>>>(ei);
    k_scan<<<1, 1024>>>();
    k_scatter<<<EG, EB>>>(ei);

    k_input<<<1024, 256>>>(x, W_in, b_in);

    for (int l = 0; l < 3; l++) {
        if (l < 2) {
            k_gemm_gat<4><<<444, 128, GEMM_SMEM>>>(Wl[l], ASl[l], ADl[l]);
            k_attnagg<4><<<AGG_BLOCKS, EB>>>();
        } else {
            k_gemm_gat<1><<<444, 128, GEMM_SMEM>>>(Wl[l], ASl[l], ADl[l]);
            k_attnagg<1><<<AGG_BLOCKS, EB>>>();
        }
        k_zero_bn<<<1, 128>>>();
        k_bnstats<<<512, 128>>>();
        k_bnapply<<<2048, 256>>>(Gl[l], Bl[l], (l < 2) ? 1 : 0);
    }

    k_mlp1<<<1024, 64>>>(Wc1, bc1);
    k_mlp2<<<(NN * 32 + EB - 1) / EB, EB>>>(Wc2, bc2, out);
}

// round 4
// speedup vs baseline: 1.5531x; 1.2838x over previous
#include <cuda_runtime.h>
#include <cuda_bf16.h>
#include <cstdint>

#define NN 50000
#define NE 800000
#define ET (NE + NN)
#define H 128
#define NTILES ((NN + 127) / 128)  // 391
#define PW 68  // smem pitch in u32 words (136 bf16 elements)

// ---------------- scratch (static __device__, no allocation) ----------------
__device__ float g_h[NN * H];
__device__ float g_lin[NN * H];
__device__ float g_agg[NN * H];
__device__ float g_ssrc[NN * 4];
__device__ float g_sdst[NN * 4];
__device__ float g_sum[H];
__device__ float g_sum2[H];
__device__ float g_hid[NN * 64];
__device__ int g_cnt[NN];
__device__ int g_rowptr[NN + 1];
__device__ int g_woff[NN];
__device__ int g_csrc[ET];

// ---------------- helpers ----------------
// split float pair -> (hi bf16x2, lo bf16x2)
__device__ __forceinline__ void split2(float a, float b, uint32_t& hi, uint32_t& lo) {
    __nv_bfloat16 ah = __float2bfloat16(a), bh = __float2bfloat16(b);
    __nv_bfloat16 al = __float2bfloat16(a - __bfloat162float(ah));
    __nv_bfloat16 bl = __float2bfloat16(b - __bfloat162float(bh));
    __nv_bfloat162 ph; ph.x = ah; ph.y = bh;
    __nv_bfloat162 pl; pl.x = al; pl.y = bl;
    hi = *reinterpret_cast<uint32_t*>(&ph);
    lo = *reinterpret_cast<uint32_t*>(&pl);
}

__device__ __forceinline__ void mma_bf16(float* c, uint32_t a0, uint32_t a1, uint32_t a2,
                                         uint32_t a3, uint32_t b0, uint32_t b1) {
    asm volatile(
        "mma.sync.aligned.m16n8k16.row.col.f32.bf16.bf16.f32 "
        "{%0,%1,%2,%3}, {%4,%5,%6,%7}, {%8,%9}, {%0,%1,%2,%3};"
        : "+f"(c[0]), "+f"(c[1]), "+f"(c[2]), "+f"(c[3])
        : "r"(a0), "r"(a1), "r"(a2), "r"(a3), "r"(b0), "r"(b1));
}

// ---------------- input layer ----------------
__global__ void k_input(const float* __restrict__ x, const float* __restrict__ W,
                        const float* __restrict__ b) {
    __shared__ float sW[H * 5];
    __shared__ float sb[H];
    for (int i = threadIdx.x; i < H * 5; i += blockDim.x) sW[i] = W[i];
    for (int i = threadIdx.x; i < H; i += blockDim.x) sb[i] = b[i];
    __syncthreads();
    int total = NN * H;
    for (int idx = blockIdx.x * blockDim.x + threadIdx.x; idx < total;
         idx += gridDim.x * blockDim.x) {
        int n = idx >> 7, c = idx & 127;
        const float* xr = x + n * 5;
        float acc = sb[c];
#pragma unroll
        for (int k = 0; k < 5; k++) acc = fmaf(xr[k], sW[c * 5 + k], acc);
        g_h[idx] = fmaxf(acc, 0.f);
    }
}

// ---------------- CSR build ----------------
__global__ void k_zero_cnt() {
    for (int i = blockIdx.x * blockDim.x + threadIdx.x; i < NN; i += gridDim.x * blockDim.x)
        g_cnt[i] = 0;
}
__global__ void k_hist(const int* __restrict__ ei) {
    int e = blockIdx.x * blockDim.x + threadIdx.x;
    if (e >= ET) return;
    int d = (e < NE) ? ei[NE + e] : e - NE;
    atomicAdd(&g_cnt[d], 1);
}
__global__ void k_scan() {
    __shared__ int sp[1024];
    const int C = (NN + 1023) / 1024;
    int t = threadIdx.x;
    int b = t * C;
    int sum = 0;
    for (int i = 0; i < C; i++) {
        int idx = b + i;
        if (idx < NN) sum += g_cnt[idx];
    }
    sp[t] = sum;
    __syncthreads();
    for (int off = 1; off < 1024; off <<= 1) {
        int v = (t >= off) ? sp[t - off] : 0;
        __syncthreads();
        sp[t] += v;
        __syncthreads();
    }
    int run = (t == 0) ? 0 : sp[t - 1];
    for (int i = 0; i < C; i++) {
        int idx = b + i;
        if (idx < NN) {
            g_rowptr[idx] = run;
            g_woff[idx] = run;
            run += g_cnt[idx];
        }
    }
    if (t == 1023) g_rowptr[NN] = run;
}
__global__ void k_scatter(const int* __restrict__ ei) {
    int e = blockIdx.x * blockDim.x + threadIdx.x;
    if (e >= ET) return;
    int s, d;
    if (e < NE) { s = ei[e]; d = ei[NE + e]; } else { s = d = e - NE; }
    int pos = atomicAdd(&g_woff[d], 1);
    g_csrc[pos] = s;
}

// ---------------- tensor-core GAT GEMM (mma.sync bf16 split) ----------------
// g_lin = g_h @ W^T; fused s_src/s_dst epilogue.
// dynamic smem: sWhi, sWlo, sAhi, sAlo each u32[128*PW]
#define GSMEM_BYTES (4 * 128 * PW * 4)
template <int HEADS>
__global__ void __launch_bounds__(256, 1) k_gemm_tc(const float* __restrict__ W,
                                                    const float* __restrict__ a_s,
                                                    const float* __restrict__ a_d) {
    extern __shared__ uint32_t smem_u[];
    uint32_t* sWhi = smem_u;
    uint32_t* sWlo = smem_u + 128 * PW;
    uint32_t* sAhi = smem_u + 2 * 128 * PW;
    uint32_t* sAlo = smem_u + 3 * 128 * PW;
    __shared__ float s_as[128], s_ad[128];
    __shared__ float s_red[2][128][2];  // HEADS==1 combine: [s/d][row][warpN]

    const int tid = threadIdx.x;
    const int wid = tid >> 5, lane = tid & 31;
    const int warpM = wid >> 1, warpN = wid & 1;
    const int g = lane >> 2, q = lane & 3;

    if (tid < 128) {
        s_as[tid] = a_s[tid];
        s_ad[tid] = a_d[tid];
    }

    // convert W once per CTA: row = tid/2, col half = (tid&1)*64
    {
        const int row = tid >> 1;
        const int ch = (tid & 1) * 64;
#pragma unroll 4
        for (int i = 0; i < 16; i++) {
            int col = ch + i * 4;
            float4 v = *reinterpret_cast<const float4*>(&W[row * 128 + col]);
            uint32_t h0, l0, h1, l1;
            split2(v.x, v.y, h0, l0);
            split2(v.z, v.w, h1, l1);
            int widx = row * PW + (col >> 1);
            *reinterpret_cast<uint2*>(&sWhi[widx]) = make_uint2(h0, h1);
            *reinterpret_cast<uint2*>(&sWlo[widx]) = make_uint2(l0, l1);
        }
    }

    for (int tile = blockIdx.x; tile < NTILES; tile += gridDim.x) {
        const int node0 = tile * 128;
        __syncthreads();  // A region free
        // convert A tile
        {
            const int row = tid >> 1;
            const int ch = (tid & 1) * 64;
            const int node = node0 + row;
#pragma unroll 4
            for (int i = 0; i < 16; i++) {
                int col = ch + i * 4;
                float4 v = (node < NN) ? *reinterpret_cast<const float4*>(&g_h[node * 128 + col])
                                       : make_float4(0.f, 0.f, 0.f, 0.f);
                uint32_t h0, l0, h1, l1;
                split2(v.x, v.y, h0, l0);
                split2(v.z, v.w, h1, l1);
                int widx = row * PW + (col >> 1);
                *reinterpret_cast<uint2*>(&sAhi[widx]) = make_uint2(h0, h1);
                *reinterpret_cast<uint2*>(&sAlo[widx]) = make_uint2(l0, l1);
            }
        }
        __syncthreads();

        float acc[2][8][4];
#pragma unroll
        for (int mt = 0; mt < 2; mt++)
#pragma unroll
            for (int nt = 0; nt < 8; nt++)
#pragma unroll
                for (int i = 0; i < 4; i++) acc[mt][nt][i] = 0.f;

#pragma unroll
        for (int ks = 0; ks < 8; ks++) {
            const int kw = ks * 8 + q;  // u32 word index along k
            // B fragments: 8 n-tiles, hi & lo
            uint32_t bh[8][2], bl[8][2];
#pragma unroll
            for (int nt = 0; nt < 8; nt++) {
                int ro = warpN * 64 + nt * 8 + g;
                int bidx = ro * PW + kw;
                bh[nt][0] = sWhi[bidx];
                bh[nt][1] = sWhi[bidx + 4];
                bl[nt][0] = sWlo[bidx];
                bl[nt][1] = sWlo[bidx + 4];
            }
#pragma unroll
            for (int mt = 0; mt < 2; mt++) {
                int ra = warpM * 32 + mt * 16 + g;
                int aidx = ra * PW + kw;
                uint32_t ah0 = sAhi[aidx], ah1 = sAhi[aidx + 8 * PW];
                uint32_t ah2 = sAhi[aidx + 4], ah3 = sAhi[aidx + 8 * PW + 4];
                uint32_t al0 = sAlo[aidx], al1 = sAlo[aidx + 8 * PW];
                uint32_t al2 = sAlo[aidx + 4], al3 = sAlo[aidx + 8 * PW + 4];
#pragma unroll
                for (int nt = 0; nt < 8; nt++) {
                    mma_bf16(acc[mt][nt], ah0, ah1, ah2, ah3, bh[nt][0], bh[nt][1]);
                    mma_bf16(acc[mt][nt], ah0, ah1, ah2, ah3, bl[nt][0], bl[nt][1]);
                    mma_bf16(acc[mt][nt], al0, al1, al2, al3, bh[nt][0], bh[nt][1]);
                }
            }
        }

        // epilogue: write g_lin + fused attention dots
        float ats[4][2], atd[4][2];  // [rowslot = mt*2+half][headslot]
#pragma unroll
        for (int s2 = 0; s2 < 4; s2++) {
            ats[s2][0] = ats[s2][1] = 0.f;
            atd[s2][0] = atd[s2][1] = 0.f;
        }
#pragma unroll
        for (int mt = 0; mt < 2; mt++) {
            const int r0 = warpM * 32 + mt * 16 + g;
            const int na = node0 + r0, nb = node0 + r0 + 8;
#pragma unroll
            for (int nt = 0; nt < 8; nt++) {
                const int colb = warpN * 64 + nt * 8 + q * 2;
                const int hs = nt >> 2;
                const float* a4 = acc[mt][nt];
                ats[mt * 2 + 0][hs] += a4[0] * s_as[colb] + a4[1] * s_as[colb + 1];
                atd[mt * 2 + 0][hs] += a4[0] * s_ad[colb] + a4[1] * s_ad[colb + 1];
                ats[mt * 2 + 1][hs] += a4[2] * s_as[colb] + a4[3] * s_as[colb + 1];
                atd[mt * 2 + 1][hs] += a4[2] * s_ad[colb] + a4[3] * s_ad[colb + 1];
                if (na < NN)
                    *reinterpret_cast<float2*>(&g_lin[na * 128 + colb]) =
                        make_float2(a4[0], a4[1]);
                if (nb < NN)
                    *reinterpret_cast<float2*>(&g_lin[nb * 128 + colb]) =
                        make_float2(a4[2], a4[3]);
            }
        }
        // reduce across the 4 lanes sharing a row (xor 1, 2)
#pragma unroll
        for (int o = 1; o <= 2; o <<= 1) {
#pragma unroll
            for (int s2 = 0; s2 < 4; s2++) {
#pragma unroll
                for (int hs = 0; hs < 2; hs++) {
                    ats[s2][hs] += __shfl_xor_sync(0xffffffffu, ats[s2][hs], o);
                    atd[s2][hs] += __shfl_xor_sync(0xffffffffu, atd[s2][hs], o);
                }
            }
        }
        if (HEADS == 4) {
            if (q == 0) {
#pragma unroll
                for (int s2 = 0; s2 < 4; s2++) {
                    int row = warpM * 32 + s2 * 8 + g;
                    int node = node0 + row;
                    if (node < NN) {
#pragma unroll
                        for (int hs = 0; hs < 2; hs++) {
                            int h = warpN * 2 + hs;
                            g_ssrc[node * 4 + h] = ats[s2][hs];
                            g_sdst[node * 4 + h] = atd[s2][hs];
                        }
                    }
                }
            }
        } else {
            if (q == 0) {
#pragma unroll
                for (int s2 = 0; s2 < 4; s2++) {
                    int row = warpM * 32 + s2 * 8 + g;
                    s_red[0][row][warpN] = ats[s2][0] + ats[s2][1];
                    s_red[1][row][warpN] = atd[s2][0] + atd[s2][1];
                }
            }
            __syncthreads();
            if (tid < 128) {
                int node = node0 + tid;
                if (node < NN) {
                    g_ssrc[node] = s_red[0][tid][0] + s_red[0][tid][1];
                    g_sdst[node] = s_red[1][tid][0] + s_red[1][tid][1];
                }
            }
        }
    }
}

// ---------------- fused attention + aggregation: warp per destination node ----------------
template <int HEADS>
__global__ void k_attnagg() {
    const int w = (blockIdx.x * blockDim.x + threadIdx.x) >> 5;
    const int lane = threadIdx.x & 31;
    if (w >= NN) return;
    const int beg = g_rowptr[w];
    const int end = g_rowptr[w + 1];

    float4 sd;
    if (HEADS == 4) sd = *reinterpret_cast<const float4*>(&g_sdst[w * 4]);
    else sd.x = g_sdst[w];

    float4 mx = make_float4(-1e30f, -1e30f, -1e30f, -1e30f);
    for (int i = beg + lane; i < end; i += 32) {
        int s = g_csrc[i];
        if (HEADS == 4) {
            float4 vs = *reinterpret_cast<const float4*>(&g_ssrc[s * 4]);
            float lx = vs.x + sd.x; lx = lx > 0.f ? lx : 0.2f * lx;
            float ly = vs.y + sd.y; ly = ly > 0.f ? ly : 0.2f * ly;
            float lz = vs.z + sd.z; lz = lz > 0.f ? lz : 0.2f * lz;
            float lw = vs.w + sd.w; lw = lw > 0.f ? lw : 0.2f * lw;
            mx.x = fmaxf(mx.x, lx); mx.y = fmaxf(mx.y, ly);
            mx.z = fmaxf(mx.z, lz); mx.w = fmaxf(mx.w, lw);
        } else {
            float l = g_ssrc[s] + sd.x;
            l = l > 0.f ? l : 0.2f * l;
            mx.x = fmaxf(mx.x, l);
        }
    }
#pragma unroll
    for (int o = 16; o > 0; o >>= 1) {
        mx.x = fmaxf(mx.x, __shfl_xor_sync(0xffffffffu, mx.x, o));
        if (HEADS == 4) {
            mx.y = fmaxf(mx.y, __shfl_xor_sync(0xffffffffu, mx.y, o));
            mx.z = fmaxf(mx.z, __shfl_xor_sync(0xffffffffu, mx.z, o));
            mx.w = fmaxf(mx.w, __shfl_xor_sync(0xffffffffu, mx.w, o));
        }
    }

    const int hd = lane >> 3;
    float4 sume = make_float4(0.f, 0.f, 0.f, 0.f);
    float4 acc = make_float4(0.f, 0.f, 0.f, 0.f);
    for (int base = beg; base < end; base += 32) {
        const int i = base + lane;
        int s = 0;
        float4 ev = make_float4(0.f, 0.f, 0.f, 0.f);
        if (i < end) {
            s = g_csrc[i];
            if (HEADS == 4) {
                float4 vs = *reinterpret_cast<const float4*>(&g_ssrc[s * 4]);
                float lx = vs.x + sd.x; lx = lx > 0.f ? lx : 0.2f * lx;
                float ly = vs.y + sd.y; ly = ly > 0.f ? ly : 0.2f * ly;
                float lz = vs.z + sd.z; lz = lz > 0.f ? lz : 0.2f * lz;
                float lw = vs.w + sd.w; lw = lw > 0.f ? lw : 0.2f * lw;
                ev.x = __expf(lx - mx.x); ev.y = __expf(ly - mx.y);
                ev.z = __expf(lz - mx.z); ev.w = __expf(lw - mx.w);
                sume.x += ev.x; sume.y += ev.y; sume.z += ev.z; sume.w += ev.w;
            } else {
                float l = g_ssrc[s] + sd.x;
                l = l > 0.f ? l : 0.2f * l;
                ev.x = __expf(l - mx.x);
                sume.x += ev.x;
            }
        }
        const int cnt = min(32, end - base);
        for (int j = 0; j < cnt; j++) {
            int sj = __shfl_sync(0xffffffffu, s, j);
            float evh;
            if (HEADS == 4) {
                float e0 = __shfl_sync(0xffffffffu, ev.x, j);
                float e1 = __shfl_sync(0xffffffffu, ev.y, j);
                float e2 = __shfl_sync(0xffffffffu, ev.z, j);
                float e3 = __shfl_sync(0xffffffffu, ev.w, j);
                evh = (hd == 0) ? e0 : (hd == 1) ? e1 : (hd == 2) ? e2 : e3;
            } else {
                evh = __shfl_sync(0xffffffffu, ev.x, j);
            }
            float4 hv = *reinterpret_cast<const float4*>(&g_lin[sj * 128 + lane * 4]);
            acc.x = fmaf(evh, hv.x, acc.x);
            acc.y = fmaf(evh, hv.y, acc.y);
            acc.z = fmaf(evh, hv.z, acc.z);
            acc.w = fmaf(evh, hv.w, acc.w);
        }
    }
#pragma unroll
    for (int o = 16; o > 0; o >>= 1) {
        sume.x += __shfl_xor_sync(0xffffffffu, sume.x, o);
        if (HEADS == 4) {
            sume.y += __shfl_xor_sync(0xffffffffu, sume.y, o);
            sume.z += __shfl_xor_sync(0xffffffffu, sume.z, o);
            sume.w += __shfl_xor_sync(0xffffffffu, sume.w, o);
        }
    }
    float dh;
    if (HEADS == 4)
        dh = (hd == 0) ? sume.x : (hd == 1) ? sume.y : (hd == 2) ? sume.z : sume.w;
    else
        dh = sume.x;
    float inv = 1.f / (dh + 1e-16f);
    acc.x *= inv; acc.y *= inv; acc.z *= inv; acc.w *= inv;
    *reinterpret_cast<float4*>(&g_agg[w * 128 + lane * 4]) = acc;
}

// ---------------- BN ----------------
__global__ void k_zero_bn() {
    if (threadIdx.x < H) {
        g_sum[threadIdx.x] = 0.f;
        g_sum2[threadIdx.x] = 0.f;
    }
}
__global__ void k_bnstats() {
    int c = threadIdx.x;
    float s = 0.f, s2 = 0.f;
    for (int n = blockIdx.x; n < NN; n += gridDim.x) {
        float v = g_agg[n * 128 + c];
        s += v;
        s2 = fmaf(v, v, s2);
    }
    atomicAdd(&g_sum[c], s);
    atomicAdd(&g_sum2[c], s2);
}
__global__ void k_bnapply(const float* __restrict__ gam, const float* __restrict__ bet,
                          int do_relu) {
    __shared__ float sc[H], sh[H];
    if (threadIdx.x < H) {
        int c = threadIdx.x;
        float mu = g_sum[c] * (1.f / NN);
        float var = g_sum2[c] * (1.f / NN) - mu * mu;
        float scale = gam[c] * rsqrtf(var + 1e-5f);
        sc[c] = scale;
        sh[c] = bet[c] - mu * scale;
    }
    __syncthreads();
    const int total = NN * H;
    for (int idx = blockIdx.x * blockDim.x + threadIdx.x; idx < total;
         idx += gridDim.x * blockDim.x) {
        int c = idx & 127;
        float v = fmaf(g_agg[idx], sc[c], sh[c]);
        g_h[idx] = do_relu ? fmaxf(v, 0.f) : v;
    }
}

// ---------------- MLP ----------------
__global__ void k_mlp1(const float* __restrict__ W, const float* __restrict__ b) {
    __shared__ float sW[64 * 129];
    __shared__ float sx[128 * 8];
    const int tid = threadIdx.x;  // 64
    for (int idx = tid; idx < 64 * 128; idx += 64) {
        int t = idx >> 7, k = idx & 127;
        sW[t * 129 + k] = W[idx];
    }
    const float bias = b[tid];
    __syncthreads();
    const int NCH = NN / 8;
    for (int chunk = blockIdx.x; chunk < NCH; chunk += gridDim.x) {
        const int n0 = chunk * 8;
        __syncthreads();
#pragma unroll
        for (int nb = 0; nb < 8; nb++)
            for (int k = tid; k < 128; k += 64) sx[k * 8 + nb] = g_h[(n0 + nb) * 128 + k];
        __syncthreads();
        float acc[8];
#pragma unroll
        for (int i = 0; i < 8; i++) acc[i] = 0.f;
#pragma unroll 4
        for (int k = 0; k < 128; k++) {
            float w = sW[tid * 129 + k];
            float4 xa = *reinterpret_cast<float4*>(&sx[k * 8]);
            float4 xb = *reinterpret_cast<float4*>(&sx[k * 8 + 4]);
            acc[0] = fmaf(w, xa.x, acc[0]);
            acc[1] = fmaf(w, xa.y, acc[1]);
            acc[2] = fmaf(w, xa.z, acc[2]);
            acc[3] = fmaf(w, xa.w, acc[3]);
            acc[4] = fmaf(w, xb.x, acc[4]);
            acc[5] = fmaf(w, xb.y, acc[5]);
            acc[6] = fmaf(w, xb.z, acc[6]);
            acc[7] = fmaf(w, xb.w, acc[7]);
        }
#pragma unroll
        for (int nb = 0; nb < 8; nb++)
            g_hid[(n0 + nb) * 64 + tid] = fmaxf(acc[nb] + bias, 0.f);
    }
}
__global__ void k_mlp2(const float* __restrict__ W, const float* __restrict__ b,
                       float* __restrict__ out) {
    __shared__ float sW[64];
    if (threadIdx.x < 64) sW[threadIdx.x] = W[threadIdx.x];
    __syncthreads();
    int n = (blockIdx.x * blockDim.x + threadIdx.x) >> 5;
    int lane = threadIdx.x & 31;
    if (n >= NN) return;
    float2 hv = *reinterpret_cast<const float2*>(&g_hid[n * 64 + lane * 2]);
    float acc = hv.x * sW[lane * 2] + hv.y * sW[lane * 2 + 1];
#pragma unroll
    for (int o = 16; o > 0; o >>= 1) acc += __shfl_xor_sync(0xffffffffu, acc, o);
    if (lane == 0) out[n] = acc + b[0];
}

// ---------------- launch ----------------
extern "C" void kernel_launch(void* const* d_in, const int* in_sizes, int n_in,
                              void* d_out, int out_size) {
    const float* x    = (const float*)d_in[0];
    const int*   ei   = (const int*)d_in[1];
    const float* W_in = (const float*)d_in[2];
    const float* b_in = (const float*)d_in[3];
    const float* Wl[3]  = {(const float*)d_in[4], (const float*)d_in[8], (const float*)d_in[12]};
    const float* ASl[3] = {(const float*)d_in[5], (const float*)d_in[9], (const float*)d_in[13]};
    const float* ADl[3] = {(const float*)d_in[6], (const float*)d_in[10], (const float*)d_in[14]};
    // GAT biases b0/b1/b2 cancel exactly in the following BatchNorm
    const float* Gl[3]  = {(const float*)d_in[16], (const float*)d_in[18], (const float*)d_in[20]};
    const float* Bl[3]  = {(const float*)d_in[17], (const float*)d_in[19], (const float*)d_in[21]};
    const float* Wc1 = (const float*)d_in[22];
    const float* bc1 = (const float*)d_in[23];
    const float* Wc2 = (const float*)d_in[24];
    const float* bc2 = (const float*)d_in[25];
    float* out = (float*)d_out;

    cudaFuncSetAttribute(k_gemm_tc<4>, cudaFuncAttributeMaxDynamicSharedMemorySize, GSMEM_BYTES);
    cudaFuncSetAttribute(k_gemm_tc<1>, cudaFuncAttributeMaxDynamicSharedMemorySize, GSMEM_BYTES);

    const int EB = 256;
    const int EG = (ET + EB - 1) / EB;
    const int AGG_BLOCKS = (NN * 32 + EB - 1) / EB;

    k_zero_cnt<<<64, 1024>>>();
    k_hist<<<EG, EB>>>(ei);
    k_scan<<<1, 1024>>>();
    k_scatter<<<EG, EB>>>(ei);

    k_input<<<1024, 256>>>(x, W_in, b_in);

    for (int l = 0; l < 3; l++) {
        if (l < 2) {
            k_gemm_tc<4><<<148, 256, GSMEM_BYTES>>>(Wl[l], ASl[l], ADl[l]);
            k_attnagg<4><<<AGG_BLOCKS, EB>>>();
        } else {
            k_gemm_tc<1><<<148, 256, GSMEM_BYTES>>>(Wl[l], ASl[l], ADl[l]);
            k_attnagg<1><<<AGG_BLOCKS, EB>>>();
        }
        k_zero_bn<<<1, 128>>>();
        k_bnstats<<<512, 128>>>();
        k_bnapply<<<2048, 256>>>(Gl[l], Bl[l], (l < 2) ? 1 : 0);
    }

    k_mlp1<<<1024, 64>>>(Wc1, bc1);
    k_mlp2<<<(NN * 32 + EB - 1) / EB, EB>>>(Wc2, bc2, out);
}

// round 7
// speedup vs baseline: 1.8374x; 1.1831x over previous
#include <cuda_runtime.h>
#include <cuda_bf16.h>
#include <cstdint>

#define NN 50000
#define NE 800000
#define ET (NE + NN)
#define H 128
#define NTILES ((NN + 127) / 128)  // 391
#define PW 68  // smem pitch in u32 words

// ---------------- scratch (static __device__, no allocation) ----------------
__device__ float g_lin[NN * H];
__device__ float g_agg[NN * H];
__device__ float g_ssrc[NN * 4];
__device__ float g_sdst[NN * 4];
__device__ float g_bnsum[3 * 128];
__device__ float g_bnsum2[3 * 128];
__device__ float g_sc[128];
__device__ float g_sh[128];
__device__ float g_hid[NN * 64];
__device__ int g_cnt[NN];
__device__ int g_rowptr[NN + 1];
__device__ int g_woff[NN];
__device__ int g_csrc[ET];

// ---------------- helpers ----------------
__device__ __forceinline__ void split2(float a, float b, uint32_t& hi, uint32_t& lo) {
    __nv_bfloat16 ah = __float2bfloat16(a), bh = __float2bfloat16(b);
    __nv_bfloat16 al = __float2bfloat16(a - __bfloat162float(ah));
    __nv_bfloat16 bl = __float2bfloat16(b - __bfloat162float(bh));
    __nv_bfloat162 ph; ph.x = ah; ph.y = bh;
    __nv_bfloat162 pl; pl.x = al; pl.y = bl;
    hi = *reinterpret_cast<uint32_t*>(&ph);
    lo = *reinterpret_cast<uint32_t*>(&pl);
}

__device__ __forceinline__ void mma_bf16(float* c, uint32_t a0, uint32_t a1, uint32_t a2,
                                         uint32_t a3, uint32_t b0, uint32_t b1) {
    asm volatile(
        "mma.sync.aligned.m16n8k16.row.col.f32.bf16.bf16.f32 "
        "{%0,%1,%2,%3}, {%4,%5,%6,%7}, {%8,%9}, {%0,%1,%2,%3};"
        : "+f"(c[0]), "+f"(c[1]), "+f"(c[2]), "+f"(c[3])
        : "r"(a0), "r"(a1), "r"(a2), "r"(a3), "r"(b0), "r"(b1));
}

// ---------------- CSR build ----------------
__global__ void k_zero_cnt() {
    int i0 = blockIdx.x * blockDim.x + threadIdx.x;
    for (int i = i0; i < NN; i += gridDim.x * blockDim.x) g_cnt[i] = 0;
    if (i0 < 3 * 128) {
        g_bnsum[i0] = 0.f;
        g_bnsum2[i0] = 0.f;
    }
}
__global__ void k_hist(const int* __restrict__ ei) {
    int e = blockIdx.x * blockDim.x + threadIdx.x;
    if (e >= ET) return;
    int d = (e < NE) ? ei[NE + e] : e - NE;
    atomicAdd(&g_cnt[d], 1);
}
__global__ void k_scan() {
    __shared__ int sp[1024];
    const int C = (NN + 1023) / 1024;
    int t = threadIdx.x;
    int b = t * C;
    int sum = 0;
    for (int i = 0; i < C; i++) {
        int idx = b + i;
        if (idx < NN) sum += g_cnt[idx];
    }
    sp[t] = sum;
    __syncthreads();
    for (int off = 1; off < 1024; off <<= 1) {
        int v = (t >= off) ? sp[t - off] : 0;
        __syncthreads();
        sp[t] += v;
        __syncthreads();
    }
    int run = (t == 0) ? 0 : sp[t - 1];
    for (int i = 0; i < C; i++) {
        int idx = b + i;
        if (idx < NN) {
            g_rowptr[idx] = run;
            g_woff[idx] = run;
            run += g_cnt[idx];
        }
    }
    if (t == 1023) g_rowptr[NN] = run;
}
__global__ void k_scatter(const int* __restrict__ ei) {
    int e = blockIdx.x * blockDim.x + threadIdx.x;
    if (e >= ET) return;
    int s, d;
    if (e < NE) { s = ei[e]; d = ei[NE + e]; } else { s = d = e - NE; }
    int pos = atomicAdd(&g_woff[d], 1);
    g_csrc[pos] = s;
}

// ---------------- BN coefficient kernel ----------------
__global__ void k_bncoef(int slot, const float* __restrict__ gam,
                         const float* __restrict__ bet) {
    int c = threadIdx.x;
    float mu = g_bnsum[slot * 128 + c] * (1.f / NN);
    float var = g_bnsum2[slot * 128 + c] * (1.f / NN) - mu * mu;
    float sc = gam[c] * rsqrtf(var + 1e-5f);
    g_sc[c] = sc;
    g_sh[c] = bet[c] - mu * sc;
}

// ---------------- tensor-core GAT GEMM (mma.sync bf16 split) ----------------
// FUSE_IN: A = relu(x @ W_in^T + b_in) computed inline from x.
// else:    A = relu(bn(g_agg)) using g_sc/g_sh.
#define GSMEM_BYTES (4 * 128 * PW * 4)
template <int HEADS, bool FUSE_IN>
__global__ void __launch_bounds__(256, 1) k_gemm_tc(const float* __restrict__ W,
                                                    const float* __restrict__ a_s,
                                                    const float* __restrict__ a_d,
                                                    const float* __restrict__ x,
                                                    const float* __restrict__ W_in,
                                                    const float* __restrict__ b_in) {
    extern __shared__ uint32_t smem_u[];
    uint32_t* sWhi = smem_u;
    uint32_t* sWlo = smem_u + 128 * PW;
    uint32_t* sAhi = smem_u + 2 * 128 * PW;
    uint32_t* sAlo = smem_u + 3 * 128 * PW;
    __shared__ float s_as[128], s_ad[128];
    __shared__ float s_red[2][128][2];
    __shared__ float s_sc[128], s_sh[128];   // BN coefs (non-input)
    __shared__ float s_xin[128 * 5];         // input-layer x tile
    __shared__ float s_win[128 * 5];
    __shared__ float s_bin[128];

    const int tid = threadIdx.x;
    const int wid = tid >> 5, lane = tid & 31;
    const int warpM = wid >> 1, warpN = wid & 1;
    const int g = lane >> 2, q = lane & 3;

    if (tid < 128) {
        s_as[tid] = a_s[tid];
        s_ad[tid] = a_d[tid];
        if (FUSE_IN) {
            s_bin[tid] = b_in[tid];
        } else {
            s_sc[tid] = g_sc[tid];
            s_sh[tid] = g_sh[tid];
        }
    }
    if (FUSE_IN) {
        for (int i = tid; i < 640; i += 256) s_win[i] = W_in[i];
    }

    // convert W once per CTA
    {
        const int row = tid >> 1;
        const int ch = (tid & 1) * 64;
#pragma unroll 4
        for (int i = 0; i < 16; i++) {
            int col = ch + i * 4;
            float4 v = *reinterpret_cast<const float4*>(&W[row * 128 + col]);
            uint32_t h0, l0, h1, l1;
            split2(v.x, v.y, h0, l0);
            split2(v.z, v.w, h1, l1);
            int widx = row * PW + (col >> 1);
            *reinterpret_cast<uint2*>(&sWhi[widx]) = make_uint2(h0, h1);
            *reinterpret_cast<uint2*>(&sWlo[widx]) = make_uint2(l0, l1);
        }
    }

    for (int tile = blockIdx.x; tile < NTILES; tile += gridDim.x) {
        const int node0 = tile * 128;
        __syncthreads();  // A region / x tile free
        if (FUSE_IN) {
            for (int i = tid; i < 640; i += 256) {
                int gi = node0 * 5 + i;
                s_xin[i] = (gi < NN * 5) ? x[gi] : 0.f;
            }
            __syncthreads();
        }
        // build A tile (bf16 hi/lo split)
        {
            const int row = tid >> 1;
            const int ch = (tid & 1) * 64;
            const int node = node0 + row;
            float x5[5];
            if (FUSE_IN) {
#pragma unroll
                for (int k = 0; k < 5; k++) x5[k] = s_xin[row * 5 + k];
            }
#pragma unroll 4
            for (int i = 0; i < 16; i++) {
                int col = ch + i * 4;
                float4 v;
                if (FUSE_IN) {
                    float c4[4];
#pragma unroll
                    for (int c = 0; c < 4; c++) {
                        float acc = s_bin[col + c];
#pragma unroll
                        for (int k = 0; k < 5; k++)
                            acc = fmaf(x5[k], s_win[(col + c) * 5 + k], acc);
                        c4[c] = fmaxf(acc, 0.f);
                    }
                    v = make_float4(c4[0], c4[1], c4[2], c4[3]);
                } else {
                    v = (node < NN) ? *reinterpret_cast<const float4*>(&g_agg[node * 128 + col])
                                    : make_float4(0.f, 0.f, 0.f, 0.f);
                    v.x = fmaxf(fmaf(v.x, s_sc[col + 0], s_sh[col + 0]), 0.f);
                    v.y = fmaxf(fmaf(v.y, s_sc[col + 1], s_sh[col + 1]), 0.f);
                    v.z = fmaxf(fmaf(v.z, s_sc[col + 2], s_sh[col + 2]), 0.f);
                    v.w = fmaxf(fmaf(v.w, s_sc[col + 3], s_sh[col + 3]), 0.f);
                }
                uint32_t h0, l0, h1, l1;
                split2(v.x, v.y, h0, l0);
                split2(v.z, v.w, h1, l1);
                int widx = row * PW + (col >> 1);
                *reinterpret_cast<uint2*>(&sAhi[widx]) = make_uint2(h0, h1);
                *reinterpret_cast<uint2*>(&sAlo[widx]) = make_uint2(l0, l1);
            }
        }
        __syncthreads();

        float acc[2][8][4];
#pragma unroll
        for (int mt = 0; mt < 2; mt++)
#pragma unroll
            for (int nt = 0; nt < 8; nt++)
#pragma unroll
                for (int i = 0; i < 4; i++) acc[mt][nt][i] = 0.f;

#pragma unroll
        for (int ks = 0; ks < 8; ks++) {
            const int kw = ks * 8 + q;
            uint32_t bh[8][2], bl[8][2];
#pragma unroll
            for (int nt = 0; nt < 8; nt++) {
                int ro = warpN * 64 + nt * 8 + g;
                int bidx = ro * PW + kw;
                bh[nt][0] = sWhi[bidx];
                bh[nt][1] = sWhi[bidx + 4];
                bl[nt][0] = sWlo[bidx];
                bl[nt][1] = sWlo[bidx + 4];
            }
#pragma unroll
            for (int mt = 0; mt < 2; mt++) {
                int ra = warpM * 32 + mt * 16 + g;
                int aidx = ra * PW + kw;
                uint32_t ah0 = sAhi[aidx], ah1 = sAhi[aidx + 8 * PW];
                uint32_t ah2 = sAhi[aidx + 4], ah3 = sAhi[aidx + 8 * PW + 4];
                uint32_t al0 = sAlo[aidx], al1 = sAlo[aidx + 8 * PW];
                uint32_t al2 = sAlo[aidx + 4], al3 = sAlo[aidx + 8 * PW + 4];
#pragma unroll
                for (int nt = 0; nt < 8; nt++) {
                    mma_bf16(acc[mt][nt], ah0, ah1, ah2, ah3, bh[nt][0], bh[nt][1]);
                    mma_bf16(acc[mt][nt], ah0, ah1, ah2, ah3, bl[nt][0], bl[nt][1]);
                    mma_bf16(acc[mt][nt], al0, al1, al2, al3, bh[nt][0], bh[nt][1]);
                }
            }
        }

        // epilogue: write g_lin + fused attention dots
        float ats[4][2], atd[4][2];
#pragma unroll
        for (int s2 = 0; s2 < 4; s2++) {
            ats[s2][0] = ats[s2][1] = 0.f;
            atd[s2][0] = atd[s2][1] = 0.f;
        }
#pragma unroll
        for (int mt = 0; mt < 2; mt++) {
            const int r0 = warpM * 32 + mt * 16 + g;
            const int na = node0 + r0, nb = node0 + r0 + 8;
#pragma unroll
            for (int nt = 0; nt < 8; nt++) {
                const int colb = warpN * 64 + nt * 8 + q * 2;
                const int hs = nt >> 2;
                const float* a4 = acc[mt][nt];
                ats[mt * 2 + 0][hs] += a4[0] * s_as[colb] + a4[1] * s_as[colb + 1];
                atd[mt * 2 + 0][hs] += a4[0] * s_ad[colb] + a4[1] * s_ad[colb + 1];
                ats[mt * 2 + 1][hs] += a4[2] * s_as[colb] + a4[3] * s_as[colb + 1];
                atd[mt * 2 + 1][hs] += a4[2] * s_ad[colb] + a4[3] * s_ad[colb + 1];
                if (na < NN)
                    *reinterpret_cast<float2*>(&g_lin[na * 128 + colb]) =
                        make_float2(a4[0], a4[1]);
                if (nb < NN)
                    *reinterpret_cast<float2*>(&g_lin[nb * 128 + colb]) =
                        make_float2(a4[2], a4[3]);
            }
        }
#pragma unroll
        for (int o = 1; o <= 2; o <<= 1) {
#pragma unroll
            for (int s2 = 0; s2 < 4; s2++) {
#pragma unroll
                for (int hs = 0; hs < 2; hs++) {
                    ats[s2][hs] += __shfl_xor_sync(0xffffffffu, ats[s2][hs], o);
                    atd[s2][hs] += __shfl_xor_sync(0xffffffffu, atd[s2][hs], o);
                }
            }
        }
        if (HEADS == 4) {
            if (q == 0) {
#pragma unroll
                for (int s2 = 0; s2 < 4; s2++) {
                    int row = warpM * 32 + s2 * 8 + g;
                    int node = node0 + row;
                    if (node < NN) {
#pragma unroll
                        for (int hs = 0; hs < 2; hs++) {
                            int h = warpN * 2 + hs;
                            g_ssrc[node * 4 + h] = ats[s2][hs];
                            g_sdst[node * 4 + h] = atd[s2][hs];
                        }
                    }
                }
            }
        } else {
            if (q == 0) {
#pragma unroll
                for (int s2 = 0; s2 < 4; s2++) {
                    int row = warpM * 32 + s2 * 8 + g;
                    s_red[0][row][warpN] = ats[s2][0] + ats[s2][1];
                    s_red[1][row][warpN] = atd[s2][0] + atd[s2][1];
                }
            }
            __syncthreads();
            if (tid < 128) {
                int node = node0 + tid;
                if (node < NN) {
                    g_ssrc[node] = s_red[0][tid][0] + s_red[0][tid][1];
                    g_sdst[node] = s_red[1][tid][0] + s_red[1][tid][1];
                }
            }
        }
    }
}

// ---------------- fused attention + aggregation + BN stats ----------------
// Single pass (softmax shift-invariance: logits O(1), no max needed).
template <int HEADS>
__global__ void k_attnagg(int slot) {
    __shared__ float bsum[128], bsum2[128];
    const int tid = threadIdx.x;
    if (tid < 128) {
        bsum[tid] = 0.f;
        bsum2[tid] = 0.f;
    }
    __syncthreads();

    const int w = (blockIdx.x * blockDim.x + tid) >> 5;
    const int lane = tid & 31;
    if (w < NN) {
        const int beg = g_rowptr[w];
        const int end = g_rowptr[w + 1];

        float4 sd;
        if (HEADS == 4) sd = *reinterpret_cast<const float4*>(&g_sdst[w * 4]);
        else sd.x = g_sdst[w];

        const int hd = lane >> 3;
        float4 sume = make_float4(0.f, 0.f, 0.f, 0.f);
        float4 acc = make_float4(0.f, 0.f, 0.f, 0.f);
        for (int base = beg; base < end; base += 32) {
            const int i = base + lane;
            int s = 0;
            float4 ev = make_float4(0.f, 0.f, 0.f, 0.f);
            if (i < end) {
                s = g_csrc[i];
                if (HEADS == 4) {
                    float4 vs = *reinterpret_cast<const float4*>(&g_ssrc[s * 4]);
                    float lx = vs.x + sd.x; lx = lx > 0.f ? lx : 0.2f * lx;
                    float ly = vs.y + sd.y; ly = ly > 0.f ? ly : 0.2f * ly;
                    float lz = vs.z + sd.z; lz = lz > 0.f ? lz : 0.2f * lz;
                    float lw = vs.w + sd.w; lw = lw > 0.f ? lw : 0.2f * lw;
                    ev.x = __expf(lx); ev.y = __expf(ly);
                    ev.z = __expf(lz); ev.w = __expf(lw);
                    sume.x += ev.x; sume.y += ev.y; sume.z += ev.z; sume.w += ev.w;
                } else {
                    float l = g_ssrc[s] + sd.x;
                    l = l > 0.f ? l : 0.2f * l;
                    ev.x = __expf(l);
                    sume.x += ev.x;
                }
            }
            const int cnt = min(32, end - base);
            for (int j = 0; j < cnt; j++) {
                int sj = __shfl_sync(0xffffffffu, s, j);
                float evh;
                if (HEADS == 4) {
                    float e0 = __shfl_sync(0xffffffffu, ev.x, j);
                    float e1 = __shfl_sync(0xffffffffu, ev.y, j);
                    float e2 = __shfl_sync(0xffffffffu, ev.z, j);
                    float e3 = __shfl_sync(0xffffffffu, ev.w, j);
                    evh = (hd == 0) ? e0 : (hd == 1) ? e1 : (hd == 2) ? e2 : e3;
                } else {
                    evh = __shfl_sync(0xffffffffu, ev.x, j);
                }
                float4 hv = *reinterpret_cast<const float4*>(&g_lin[sj * 128 + lane * 4]);
                acc.x = fmaf(evh, hv.x, acc.x);
                acc.y = fmaf(evh, hv.y, acc.y);
                acc.z = fmaf(evh, hv.z, acc.z);
                acc.w = fmaf(evh, hv.w, acc.w);
            }
        }
#pragma unroll
        for (int o = 16; o > 0; o >>= 1) {
            sume.x += __shfl_xor_sync(0xffffffffu, sume.x, o);
            if (HEADS == 4) {
                sume.y += __shfl_xor_sync(0xffffffffu, sume.y, o);
                sume.z += __shfl_xor_sync(0xffffffffu, sume.z, o);
                sume.w += __shfl_xor_sync(0xffffffffu, sume.w, o);
            }
        }
        float dh;
        if (HEADS == 4)
            dh = (hd == 0) ? sume.x : (hd == 1) ? sume.y : (hd == 2) ? sume.z : sume.w;
        else
            dh = sume.x;
        float inv = 1.f / (dh + 1e-16f);
        acc.x *= inv; acc.y *= inv; acc.z *= inv; acc.w *= inv;
        *reinterpret_cast<float4*>(&g_agg[w * 128 + lane * 4]) = acc;

        // BN stats into block-shared accumulators
        const int c0 = lane * 4;
        atomicAdd(&bsum[c0 + 0], acc.x);
        atomicAdd(&bsum[c0 + 1], acc.y);
        atomicAdd(&bsum[c0 + 2], acc.z);
        atomicAdd(&bsum[c0 + 3], acc.w);
        atomicAdd(&bsum2[c0 + 0], acc.x * acc.x);
        atomicAdd(&bsum2[c0 + 1], acc.y * acc.y);
        atomicAdd(&bsum2[c0 + 2], acc.z * acc.z);
        atomicAdd(&bsum2[c0 + 3], acc.w * acc.w);
    }
    __syncthreads();
    if (tid < 128) {
        atomicAdd(&g_bnsum[slot * 128 + tid], bsum[tid]);
        atomicAdd(&g_bnsum2[slot * 128 + tid], bsum2[tid]);
    }
}

// ---------------- MLP layer 1 (fused BN, no relu on BN): hid = relu(bn(agg) @ Wc1^T + bc1) ----------------
__global__ void k_mlp1(const float* __restrict__ W, const float* __restrict__ b) {
    __shared__ float sW[64 * 129];
    __shared__ float sx[128 * 8];
    __shared__ float s_sc[128], s_sh[128];
    const int tid = threadIdx.x;  // 64
    for (int idx = tid; idx < 64 * 128; idx += 64) {
        int t = idx >> 7, k = idx & 127;
        sW[t * 129 + k] = W[idx];
    }
    for (int idx = tid; idx < 128; idx += 64) {
        s_sc[idx] = g_sc[idx];
        s_sh[idx] = g_sh[idx];
    }
    const float bias = b[tid];
    __syncthreads();
    const int NCH = NN / 8;
    for (int chunk = blockIdx.x; chunk < NCH; chunk += gridDim.x) {
        const int n0 = chunk * 8;
        __syncthreads();
#pragma unroll
        for (int nb = 0; nb < 8; nb++)
            for (int k = tid; k < 128; k += 64)
                sx[k * 8 + nb] = fmaf(g_agg[(n0 + nb) * 128 + k], s_sc[k], s_sh[k]);
        __syncthreads();
        float acc[8];
#pragma unroll
        for (int i = 0; i < 8; i++) acc[i] = 0.f;
#pragma unroll 4
        for (int k = 0; k < 128; k++) {
            float w = sW[tid * 129 + k];
            float4 xa = *reinterpret_cast<float4*>(&sx[k * 8]);
            float4 xb = *reinterpret_cast<float4*>(&sx[k * 8 + 4]);
            acc[0] = fmaf(w, xa.x, acc[0]);
            acc[1] = fmaf(w, xa.y, acc[1]);
            acc[2] = fmaf(w, xa.z, acc[2]);
            acc[3] = fmaf(w, xa.w, acc[3]);
            acc[4] = fmaf(w, xb.x, acc[4]);
            acc[5] = fmaf(w, xb.y, acc[5]);
            acc[6] = fmaf(w, xb.z, acc[6]);
            acc[7] = fmaf(w, xb.w, acc[7]);
        }
#pragma unroll
        for (int nb = 0; nb < 8; nb++)
            g_hid[(n0 + nb) * 64 + tid] = fmaxf(acc[nb] + bias, 0.f);
    }
}
__global__ void k_mlp2(const float* __restrict__ W, const float* __restrict__ b,
                       float* __restrict__ out) {
    __shared__ float sW[64];
    if (threadIdx.x < 64) sW[threadIdx.x] = W[threadIdx.x];
    __syncthreads();
    int n = (blockIdx.x * blockDim.x + threadIdx.x) >> 5;
    int lane = threadIdx.x & 31;
    if (n >= NN) return;
    float2 hv = *reinterpret_cast<const float2*>(&g_hid[n * 64 + lane * 2]);
    float acc = hv.x * sW[lane * 2] + hv.y * sW[lane * 2 + 1];
#pragma unroll
    for (int o = 16; o > 0; o >>= 1) acc += __shfl_xor_sync(0xffffffffu, acc, o);
    if (lane == 0) out[n] = acc + b[0];
}

// ---------------- launch ----------------
extern "C" void kernel_launch(void* const* d_in, const int* in_sizes, int n_in,
                              void* d_out, int out_size) {
    const float* x    = (const float*)d_in[0];
    const int*   ei   = (const int*)d_in[1];
    const float* W_in = (const float*)d_in[2];
    const float* b_in = (const float*)d_in[3];
    const float* Wl[3]  = {(const float*)d_in[4], (const float*)d_in[8], (const float*)d_in[12]};
    const float* ASl[3] = {(const float*)d_in[5], (const float*)d_in[9], (const float*)d_in[13]};
    const float* ADl[3] = {(const float*)d_in[6], (const float*)d_in[10], (const float*)d_in[14]};
    // GAT biases b0/b1/b2 cancel exactly in the following BatchNorm
    const float* Gl[3]  = {(const float*)d_in[16], (const float*)d_in[18], (const float*)d_in[20]};
    const float* Bl[3]  = {(const float*)d_in[17], (const float*)d_in[19], (const float*)d_in[21]};
    const float* Wc1 = (const float*)d_in[22];
    const float* bc1 = (const float*)d_in[23];
    const float* Wc2 = (const float*)d_in[24];
    const float* bc2 = (const float*)d_in[25];
    float* out = (float*)d_out;

    cudaFuncSetAttribute(k_gemm_tc<4, true>, cudaFuncAttributeMaxDynamicSharedMemorySize, GSMEM_BYTES);
    cudaFuncSetAttribute(k_gemm_tc<4, false>, cudaFuncAttributeMaxDynamicSharedMemorySize, GSMEM_BYTES);
    cudaFuncSetAttribute(k_gemm_tc<1, false>, cudaFuncAttributeMaxDynamicSharedMemorySize, GSMEM_BYTES);

    const int EB = 256;
    const int EG = (ET + EB - 1) / EB;
    const int AGG_BLOCKS = NN * 32 / EB;  // 6250 exact

    k_zero_cnt<<<64, 1024>>>();
    k_hist<<<EG, EB>>>(ei);
    k_scan<<<1, 1024>>>();
    k_scatter<<<EG, EB>>>(ei);

    // layer 0 (input fused)
    k_gemm_tc<4, true><<<148, 256, GSMEM_BYTES>>>(Wl[0], ASl[0], ADl[0], x, W_in, b_in);
    k_attnagg<4><<<AGG_BLOCKS, EB>>>(0);
    k_bncoef<<<1, 128>>>(0, Gl[0], Bl[0]);
    // layer 1 (BN+relu fused into A-load)
    k_gemm_tc<4, false><<<148, 256, GSMEM_BYTES>>>(Wl[1], ASl[1], ADl[1], x, W_in, b_in);
    k_attnagg<4><<<AGG_BLOCKS, EB>>>(1);
    k_bncoef<<<1, 128>>>(1, Gl[1], Bl[1]);
    // layer 2
    k_gemm_tc<1, false><<<148, 256, GSMEM_BYTES>>>(Wl[2], ASl[2], ADl[2], x, W_in, b_in);
    k_attnagg<1><<<AGG_BLOCKS, EB>>>(2);
    k_bncoef<<<1, 128>>>(2, Gl[2], Bl[2]);
    // MLP head (BN of layer 2 fused, no relu on BN)
    k_mlp1<<<1024, 64>>>(Wc1, bc1);
    k_mlp2<<<NN * 32 / EB, EB>>>(Wc2, bc2, out);
}

// round 9
// speedup vs baseline: 1.9258x; 1.0481x over previous
#include <cuda_runtime.h>
#include <cuda_bf16.h>
#include <cuda_fp16.h>
#include <cstdint>

#define NN 50000
#define NE 800000
#define ET (NE + NN)
#define H 128
#define NTILES ((NN + 127) / 128)  // 391
#define PW 68  // smem pitch in u32 words

// ---------------- scratch (static __device__, no allocation) ----------------
__device__ __half g_lin[NN * H];   // fp16 value matrix for aggregation gather
__device__ float g_agg[NN * H];
__device__ float g_ssrc[NN * 4];
__device__ float g_sdst[NN * 4];
__device__ float g_bnsum[3 * 128];
__device__ float g_bnsum2[3 * 128];
__device__ float g_sc[128];
__device__ float g_sh[128];
__device__ float g_hid[NN * 64];
__device__ int g_cnt[NN];
__device__ int g_rowptr[NN + 1];
__device__ int g_woff[NN];
__device__ int g_csrc[ET];

// ---------------- helpers ----------------
__device__ __forceinline__ void split2(float a, float b, uint32_t& hi, uint32_t& lo) {
    __nv_bfloat16 ah = __float2bfloat16(a), bh = __float2bfloat16(b);
    __nv_bfloat16 al = __float2bfloat16(a - __bfloat162float(ah));
    __nv_bfloat16 bl = __float2bfloat16(b - __bfloat162float(bh));
    __nv_bfloat162 ph; ph.x = ah; ph.y = bh;
    __nv_bfloat162 pl; pl.x = al; pl.y = bl;
    hi = *reinterpret_cast<uint32_t*>(&ph);
    lo = *reinterpret_cast<uint32_t*>(&pl);
}

__device__ __forceinline__ void mma_bf16(float* c, uint32_t a0, uint32_t a1, uint32_t a2,
                                         uint32_t a3, uint32_t b0, uint32_t b1) {
    asm volatile(
        "mma.sync.aligned.m16n8k16.row.col.f32.bf16.bf16.f32 "
        "{%0,%1,%2,%3}, {%4,%5,%6,%7}, {%8,%9}, {%0,%1,%2,%3};"
        : "+f"(c[0]), "+f"(c[1]), "+f"(c[2]), "+f"(c[3])
        : "r"(a0), "r"(a1), "r"(a2), "r"(a3), "r"(b0), "r"(b1));
}

// ---------------- CSR build ----------------
__global__ void k_zero_cnt() {
    int i0 = blockIdx.x * blockDim.x + threadIdx.x;
    for (int i = i0; i < NN; i += gridDim.x * blockDim.x) g_cnt[i] = 0;
    if (i0 < 3 * 128) {
        g_bnsum[i0] = 0.f;
        g_bnsum2[i0] = 0.f;
    }
}
__global__ void k_hist(const int* __restrict__ ei) {
    int e = blockIdx.x * blockDim.x + threadIdx.x;
    if (e >= ET) return;
    int d = (e < NE) ? ei[NE + e] : e - NE;
    atomicAdd(&g_cnt[d], 1);
}
__global__ void k_scan() {
    __shared__ int sp[1024];
    const int C = (NN + 1023) / 1024;
    int t = threadIdx.x;
    int b = t * C;
    int sum = 0;
    for (int i = 0; i < C; i++) {
        int idx = b + i;
        if (idx < NN) sum += g_cnt[idx];
    }
    sp[t] = sum;
    __syncthreads();
    for (int off = 1; off < 1024; off <<= 1) {
        int v = (t >= off) ? sp[t - off] : 0;
        __syncthreads();
        sp[t] += v;
        __syncthreads();
    }
    int run = (t == 0) ? 0 : sp[t - 1];
    for (int i = 0; i < C; i++) {
        int idx = b + i;
        if (idx < NN) {
            g_rowptr[idx] = run;
            g_woff[idx] = run;
            run += g_cnt[idx];
        }
    }
    if (t == 1023) g_rowptr[NN] = run;
}
__global__ void k_scatter(const int* __restrict__ ei) {
    int e = blockIdx.x * blockDim.x + threadIdx.x;
    if (e >= ET) return;
    int s, d;
    if (e < NE) { s = ei[e]; d = ei[NE + e]; } else { s = d = e - NE; }
    int pos = atomicAdd(&g_woff[d], 1);
    g_csrc[pos] = s;
}

// ---------------- BN coefficient kernel ----------------
__global__ void k_bncoef(int slot, const float* __restrict__ gam,
                         const float* __restrict__ bet) {
    int c = threadIdx.x;
    float mu = g_bnsum[slot * 128 + c] * (1.f / NN);
    float var = g_bnsum2[slot * 128 + c] * (1.f / NN) - mu * mu;
    float sc = gam[c] * rsqrtf(var + 1e-5f);
    g_sc[c] = sc;
    g_sh[c] = bet[c] - mu * sc;
}

// ---------------- tensor-core GAT GEMM (mma.sync bf16 split) ----------------
// FUSE_IN: A = relu(x @ W_in^T + b_in) computed inline from x.
// else:    A = relu(bn(g_agg)) using g_sc/g_sh.
#define GSMEM_BYTES (4 * 128 * PW * 4)
template <int HEADS, bool FUSE_IN>
__global__ void __launch_bounds__(256, 1) k_gemm_tc(const float* __restrict__ W,
                                                    const float* __restrict__ a_s,
                                                    const float* __restrict__ a_d,
                                                    const float* __restrict__ x,
                                                    const float* __restrict__ W_in,
                                                    const float* __restrict__ b_in) {
    extern __shared__ uint32_t smem_u[];
    uint32_t* sWhi = smem_u;
    uint32_t* sWlo = smem_u + 128 * PW;
    uint32_t* sAhi = smem_u + 2 * 128 * PW;
    uint32_t* sAlo = smem_u + 3 * 128 * PW;
    __shared__ float s_as[128], s_ad[128];
    __shared__ float s_red[2][128][2];
    __shared__ float s_sc[128], s_sh[128];   // BN coefs (non-input)
    __shared__ float s_xin[128 * 5];         // input-layer x tile
    __shared__ float s_win[128 * 5];
    __shared__ float s_bin[128];

    const int tid = threadIdx.x;
    const int wid = tid >> 5, lane = tid & 31;
    const int warpM = wid >> 1, warpN = wid & 1;
    const int g = lane >> 2, q = lane & 3;

    if (tid < 128) {
        s_as[tid] = a_s[tid];
        s_ad[tid] = a_d[tid];
        if (FUSE_IN) {
            s_bin[tid] = b_in[tid];
        } else {
            s_sc[tid] = g_sc[tid];
            s_sh[tid] = g_sh[tid];
        }
    }
    if (FUSE_IN) {
        for (int i = tid; i < 640; i += 256) s_win[i] = W_in[i];
    }

    // convert W once per CTA
    {
        const int row = tid >> 1;
        const int ch = (tid & 1) * 64;
#pragma unroll 4
        for (int i = 0; i < 16; i++) {
            int col = ch + i * 4;
            float4 v = *reinterpret_cast<const float4*>(&W[row * 128 + col]);
            uint32_t h0, l0, h1, l1;
            split2(v.x, v.y, h0, l0);
            split2(v.z, v.w, h1, l1);
            int widx = row * PW + (col >> 1);
            *reinterpret_cast<uint2*>(&sWhi[widx]) = make_uint2(h0, h1);
            *reinterpret_cast<uint2*>(&sWlo[widx]) = make_uint2(l0, l1);
        }
    }

    for (int tile = blockIdx.x; tile < NTILES; tile += gridDim.x) {
        const int node0 = tile * 128;
        __syncthreads();  // A region / x tile free
        if (FUSE_IN) {
            for (int i = tid; i < 640; i += 256) {
                int gi = node0 * 5 + i;
                s_xin[i] = (gi < NN * 5) ? x[gi] : 0.f;
            }
            __syncthreads();
        }
        // build A tile (bf16 hi/lo split)
        {
            const int row = tid >> 1;
            const int ch = (tid & 1) * 64;
            const int node = node0 + row;
            float x5[5];
            if (FUSE_IN) {
#pragma unroll
                for (int k = 0; k < 5; k++) x5[k] = s_xin[row * 5 + k];
            }
#pragma unroll 4
            for (int i = 0; i < 16; i++) {
                int col = ch + i * 4;
                float4 v;
                if (FUSE_IN) {
                    float c4[4];
#pragma unroll
                    for (int c = 0; c < 4; c++) {
                        float acc = s_bin[col + c];
#pragma unroll
                        for (int k = 0; k < 5; k++)
                            acc = fmaf(x5[k], s_win[(col + c) * 5 + k], acc);
                        c4[c] = fmaxf(acc, 0.f);
                    }
                    v = make_float4(c4[0], c4[1], c4[2], c4[3]);
                } else {
                    v = (node < NN) ? *reinterpret_cast<const float4*>(&g_agg[node * 128 + col])
                                    : make_float4(0.f, 0.f, 0.f, 0.f);
                    v.x = fmaxf(fmaf(v.x, s_sc[col + 0], s_sh[col + 0]), 0.f);
                    v.y = fmaxf(fmaf(v.y, s_sc[col + 1], s_sh[col + 1]), 0.f);
                    v.z = fmaxf(fmaf(v.z, s_sc[col + 2], s_sh[col + 2]), 0.f);
                    v.w = fmaxf(fmaf(v.w, s_sc[col + 3], s_sh[col + 3]), 0.f);
                }
                uint32_t h0, l0, h1, l1;
                split2(v.x, v.y, h0, l0);
                split2(v.z, v.w, h1, l1);
                int widx = row * PW + (col >> 1);
                *reinterpret_cast<uint2*>(&sAhi[widx]) = make_uint2(h0, h1);
                *reinterpret_cast<uint2*>(&sAlo[widx]) = make_uint2(l0, l1);
            }
        }
        __syncthreads();

        float acc[2][8][4];
#pragma unroll
        for (int mt = 0; mt < 2; mt++)
#pragma unroll
            for (int nt = 0; nt < 8; nt++)
#pragma unroll
                for (int i = 0; i < 4; i++) acc[mt][nt][i] = 0.f;

#pragma unroll
        for (int ks = 0; ks < 8; ks++) {
            const int kw = ks * 8 + q;
            uint32_t bh[8][2], bl[8][2];
#pragma unroll
            for (int nt = 0; nt < 8; nt++) {
                int ro = warpN * 64 + nt * 8 + g;
                int bidx = ro * PW + kw;
                bh[nt][0] = sWhi[bidx];
                bh[nt][1] = sWhi[bidx + 4];
                bl[nt][0] = sWlo[bidx];
                bl[nt][1] = sWlo[bidx + 4];
            }
#pragma unroll
            for (int mt = 0; mt < 2; mt++) {
                int ra = warpM * 32 + mt * 16 + g;
                int aidx = ra * PW + kw;
                uint32_t ah0 = sAhi[aidx], ah1 = sAhi[aidx + 8 * PW];
                uint32_t ah2 = sAhi[aidx + 4], ah3 = sAhi[aidx + 8 * PW + 4];
                uint32_t al0 = sAlo[aidx], al1 = sAlo[aidx + 8 * PW];
                uint32_t al2 = sAlo[aidx + 4], al3 = sAlo[aidx + 8 * PW + 4];
#pragma unroll
                for (int nt = 0; nt < 8; nt++) {
                    mma_bf16(acc[mt][nt], ah0, ah1, ah2, ah3, bh[nt][0], bh[nt][1]);
                    mma_bf16(acc[mt][nt], ah0, ah1, ah2, ah3, bl[nt][0], bl[nt][1]);
                    mma_bf16(acc[mt][nt], al0, al1, al2, al3, bh[nt][0], bh[nt][1]);
                }
            }
        }

        // epilogue: write g_lin (fp16) + fused attention dots (fp32)
        float ats[4][2], atd[4][2];
#pragma unroll
        for (int s2 = 0; s2 < 4; s2++) {
            ats[s2][0] = ats[s2][1] = 0.f;
            atd[s2][0] = atd[s2][1] = 0.f;
        }
#pragma unroll
        for (int mt = 0; mt < 2; mt++) {
            const int r0 = warpM * 32 + mt * 16 + g;
            const int na = node0 + r0, nb = node0 + r0 + 8;
#pragma unroll
            for (int nt = 0; nt < 8; nt++) {
                const int colb = warpN * 64 + nt * 8 + q * 2;
                const int hs = nt >> 2;
                const float* a4 = acc[mt][nt];
                ats[mt * 2 + 0][hs] += a4[0] * s_as[colb] + a4[1] * s_as[colb + 1];
                atd[mt * 2 + 0][hs] += a4[0] * s_ad[colb] + a4[1] * s_ad[colb + 1];
                ats[mt * 2 + 1][hs] += a4[2] * s_as[colb] + a4[3] * s_as[colb + 1];
                atd[mt * 2 + 1][hs] += a4[2] * s_ad[colb] + a4[3] * s_ad[colb + 1];
                if (na < NN)
                    *reinterpret_cast<__half2*>(&g_lin[na * 128 + colb]) =
                        __floats2half2_rn(a4[0], a4[1]);
                if (nb < NN)
                    *reinterpret_cast<__half2*>(&g_lin[nb * 128 + colb]) =
                        __floats2half2_rn(a4[2], a4[3]);
            }
        }
#pragma unroll
        for (int o = 1; o <= 2; o <<= 1) {
#pragma unroll
            for (int s2 = 0; s2 < 4; s2++) {
#pragma unroll
                for (int hs = 0; hs < 2; hs++) {
                    ats[s2][hs] += __shfl_xor_sync(0xffffffffu, ats[s2][hs], o);
                    atd[s2][hs] += __shfl_xor_sync(0xffffffffu, atd[s2][hs], o);
                }
            }
        }
        if (HEADS == 4) {
            if (q == 0) {
#pragma unroll
                for (int s2 = 0; s2 < 4; s2++) {
                    int row = warpM * 32 + s2 * 8 + g;
                    int node = node0 + row;
                    if (node < NN) {
#pragma unroll
                        for (int hs = 0; hs < 2; hs++) {
                            int h = warpN * 2 + hs;
                            g_ssrc[node * 4 + h] = ats[s2][hs];
                            g_sdst[node * 4 + h] = atd[s2][hs];
                        }
                    }
                }
            }
        } else {
            if (q == 0) {
#pragma unroll
                for (int s2 = 0; s2 < 4; s2++) {
                    int row = warpM * 32 + s2 * 8 + g;
                    s_red[0][row][warpN] = ats[s2][0] + ats[s2][1];
                    s_red[1][row][warpN] = atd[s2][0] + atd[s2][1];
                }
            }
            __syncthreads();
            if (tid < 128) {
                int node = node0 + tid;
                if (node < NN) {
                    g_ssrc[node] = s_red[0][tid][0] + s_red[0][tid][1];
                    g_sdst[node] = s_red[1][tid][0] + s_red[1][tid][1];
                }
            }
        }
    }
}

// ---------------- fused attention + aggregation + BN stats ----------------
template <int HEADS>
__global__ void k_attnagg(int slot) {
    __shared__ float bsum[128], bsum2[128];
    const int tid = threadIdx.x;
    if (tid < 128) {
        bsum[tid] = 0.f;
        bsum2[tid] = 0.f;
    }
    __syncthreads();

    const int w = (blockIdx.x * blockDim.x + tid) >> 5;
    const int lane = tid & 31;
    if (w < NN) {
        const int beg = g_rowptr[w];
        const int end = g_rowptr[w + 1];

        float4 sd;
        if (HEADS == 4) sd = *reinterpret_cast<const float4*>(&g_sdst[w * 4]);
        else sd.x = g_sdst[w];

        const int hd = lane >> 3;
        float4 sume = make_float4(0.f, 0.f, 0.f, 0.f);
        float4 acc = make_float4(0.f, 0.f, 0.f, 0.f);
        for (int base = beg; base < end; base += 32) {
            const int i = base + lane;
            int s = 0;
            float4 ev = make_float4(0.f, 0.f, 0.f, 0.f);
            if (i < end) {
                s = g_csrc[i];
                if (HEADS == 4) {
                    float4 vs = *reinterpret_cast<const float4*>(&g_ssrc[s * 4]);
                    float lx = vs.x + sd.x; lx = lx > 0.f ? lx : 0.2f * lx;
                    float ly = vs.y + sd.y; ly = ly > 0.f ? ly : 0.2f * ly;
                    float lz = vs.z + sd.z; lz = lz > 0.f ? lz : 0.2f * lz;
                    float lw = vs.w + sd.w; lw = lw > 0.f ? lw : 0.2f * lw;
                    ev.x = __expf(lx); ev.y = __expf(ly);
                    ev.z = __expf(lz); ev.w = __expf(lw);
                    sume.x += ev.x; sume.y += ev.y; sume.z += ev.z; sume.w += ev.w;
                } else {
                    float l = g_ssrc[s] + sd.x;
                    l = l > 0.f ? l : 0.2f * l;
                    ev.x = __expf(l);
                    sume.x += ev.x;
                }
            }
            const int cnt = min(32, end - base);
            for (int j = 0; j < cnt; j++) {
                int sj = __shfl_sync(0xffffffffu, s, j);
                float evh;
                if (HEADS == 4) {
                    float e0 = __shfl_sync(0xffffffffu, ev.x, j);
                    float e1 = __shfl_sync(0xffffffffu, ev.y, j);
                    float e2 = __shfl_sync(0xffffffffu, ev.z, j);
                    float e3 = __shfl_sync(0xffffffffu, ev.w, j);
                    evh = (hd == 0) ? e0 : (hd == 1) ? e1 : (hd == 2) ? e2 : e3;
                } else {
                    evh = __shfl_sync(0xffffffffu, ev.x, j);
                }
                // fp16 gather: 4 channels = 8B per lane
                uint2 raw = *reinterpret_cast<const uint2*>(&g_lin[sj * 128 + lane * 4]);
                float2 f01 = __half22float2(*reinterpret_cast<__half2*>(&raw.x));
                float2 f23 = __half22float2(*reinterpret_cast<__half2*>(&raw.y));
                acc.x = fmaf(evh, f01.x, acc.x);
                acc.y = fmaf(evh, f01.y, acc.y);
                acc.z = fmaf(evh, f23.x, acc.z);
                acc.w = fmaf(evh, f23.y, acc.w);
            }
        }
#pragma unroll
        for (int o = 16; o > 0; o >>= 1) {
            sume.x += __shfl_xor_sync(0xffffffffu, sume.x, o);
            if (HEADS == 4) {
                sume.y += __shfl_xor_sync(0xffffffffu, sume.y, o);
                sume.z += __shfl_xor_sync(0xffffffffu, sume.z, o);
                sume.w += __shfl_xor_sync(0xffffffffu, sume.w, o);
            }
        }
        float dh;
        if (HEADS == 4)
            dh = (hd == 0) ? sume.x : (hd == 1) ? sume.y : (hd == 2) ? sume.z : sume.w;
        else
            dh = sume.x;
        float inv = 1.f / (dh + 1e-16f);
        acc.x *= inv; acc.y *= inv; acc.z *= inv; acc.w *= inv;
        *reinterpret_cast<float4*>(&g_agg[w * 128 + lane * 4]) = acc;

        const int c0 = lane * 4;
        atomicAdd(&bsum[c0 + 0], acc.x);
        atomicAdd(&bsum[c0 + 1], acc.y);
        atomicAdd(&bsum[c0 + 2], acc.z);
        atomicAdd(&bsum[c0 + 3], acc.w);
        atomicAdd(&bsum2[c0 + 0], acc.x * acc.x);
        atomicAdd(&bsum2[c0 + 1], acc.y * acc.y);
        atomicAdd(&bsum2[c0 + 2], acc.z * acc.z);
        atomicAdd(&bsum2[c0 + 3], acc.w * acc.w);
    }
    __syncthreads();
    if (tid < 128) {
        atomicAdd(&g_bnsum[slot * 128 + tid], bsum[tid]);
        atomicAdd(&g_bnsum2[slot * 128 + tid], bsum2[tid]);
    }
}

// ---------------- MLP layer 1 (fused BN): hid = relu(bn(agg) @ Wc1^T + bc1) ----------------
__global__ void k_mlp1(const float* __restrict__ W, const float* __restrict__ b) {
    __shared__ float sW[64 * 129];
    __shared__ float sx[128 * 8];
    __shared__ float s_sc[128], s_sh[128];
    const int tid = threadIdx.x;  // 64
    for (int idx = tid; idx < 64 * 128; idx += 64) {
        int t = idx >> 7, k = idx & 127;
        sW[t * 129 + k] = W[idx];
    }
    for (int idx = tid; idx < 128; idx += 64) {
        s_sc[idx] = g_sc[idx];
        s_sh[idx] = g_sh[idx];
    }
    const float bias = b[tid];
    __syncthreads();
    const int NCH = NN / 8;
    for (int chunk = blockIdx.x; chunk < NCH; chunk += gridDim.x) {
        const int n0 = chunk * 8;
        __syncthreads();
#pragma unroll
        for (int nb = 0; nb < 8; nb++)
            for (int k = tid; k < 128; k += 64)
                sx[k * 8 + nb] = fmaf(g_agg[(n0 + nb) * 128 + k], s_sc[k], s_sh[k]);
        __syncthreads();
        float acc[8];
#pragma unroll
        for (int i = 0; i < 8; i++) acc[i] = 0.f;
#pragma unroll 4
        for (int k = 0; k < 128; k++) {
            float w = sW[tid * 129 + k];
            float4 xa = *reinterpret_cast<float4*>(&sx[k * 8]);
            float4 xb = *reinterpret_cast<float4*>(&sx[k * 8 + 4]);
            acc[0] = fmaf(w, xa.x, acc[0]);
            acc[1] = fmaf(w, xa.y, acc[1]);
            acc[2] = fmaf(w, xa.z, acc[2]);
            acc[3] = fmaf(w, xa.w, acc[3]);
            acc[4] = fmaf(w, xb.x, acc[4]);
            acc[5] = fmaf(w, xb.y, acc[5]);
            acc[6] = fmaf(w, xb.z, acc[6]);
            acc[7] = fmaf(w, xb.w, acc[7]);
        }
#pragma unroll
        for (int nb = 0; nb < 8; nb++)
            g_hid[(n0 + nb) * 64 + tid] = fmaxf(acc[nb] + bias, 0.f);
    }
}
__global__ void k_mlp2(const float* __restrict__ W, const float* __restrict__ b,
                       float* __restrict__ out) {
    __shared__ float sW[64];
    if (threadIdx.x < 64) sW[threadIdx.x] = W[threadIdx.x];
    __syncthreads();
    int n = (blockIdx.x * blockDim.x + threadIdx.x) >> 5;
    int lane = threadIdx.x & 31;
    if (n >= NN) return;
    float2 hv = *reinterpret_cast<const float2*>(&g_hid[n * 64 + lane * 2]);
    float acc = hv.x * sW[lane * 2] + hv.y * sW[lane * 2 + 1];
#pragma unroll
    for (int o = 16; o > 0; o >>= 1) acc += __shfl_xor_sync(0xffffffffu, acc, o);
    if (lane == 0) out[n] = acc + b[0];
}

// ---------------- launch ----------------
extern "C" void kernel_launch(void* const* d_in, const int* in_sizes, int n_in,
                              void* d_out, int out_size) {
    const float* x    = (const float*)d_in[0];
    const int*   ei   = (const int*)d_in[1];
    const float* W_in = (const float*)d_in[2];
    const float* b_in = (const float*)d_in[3];
    const float* Wl[3]  = {(const float*)d_in[4], (const float*)d_in[8], (const float*)d_in[12]};
    const float* ASl[3] = {(const float*)d_in[5], (const float*)d_in[9], (const float*)d_in[13]};
    const float* ADl[3] = {(const float*)d_in[6], (const float*)d_in[10], (const float*)d_in[14]};
    // GAT biases b0/b1/b2 cancel exactly in the following BatchNorm
    const float* Gl[3]  = {(const float*)d_in[16], (const float*)d_in[18], (const float*)d_in[20]};
    const float* Bl[3]  = {(const float*)d_in[17], (const float*)d_in[19], (const float*)d_in[21]};
    const float* Wc1 = (const float*)d_in[22];
    const float* bc1 = (const float*)d_in[23];
    const float* Wc2 = (const float*)d_in[24];
    const float* bc2 = (const float*)d_in[25];
    float* out = (float*)d_out;

    cudaFuncSetAttribute(k_gemm_tc<4, true>, cudaFuncAttributeMaxDynamicSharedMemorySize, GSMEM_BYTES);
    cudaFuncSetAttribute(k_gemm_tc<4, false>, cudaFuncAttributeMaxDynamicSharedMemorySize, GSMEM_BYTES);
    cudaFuncSetAttribute(k_gemm_tc<1, false>, cudaFuncAttributeMaxDynamicSharedMemorySize, GSMEM_BYTES);

    const int EB = 256;
    const int EG = (ET + EB - 1) / EB;
    const int AGG_BLOCKS = NN * 32 / EB;  // 6250 exact

    k_zero_cnt<<<64, 1024>>>();
    k_hist<<<EG, EB>>>(ei);
    k_scan<<<1, 1024>>>();
    k_scatter<<<EG, EB>>>(ei);

    // layer 0 (input fused)
    k_gemm_tc<4, true><<<148, 256, GSMEM_BYTES>>>(Wl[0], ASl[0], ADl[0], x, W_in, b_in);
    k_attnagg<4><<<AGG_BLOCKS, EB>>>(0);
    k_bncoef<<<1, 128>>>(0, Gl[0], Bl[0]);
    // layer 1 (BN+relu fused into A-load)
    k_gemm_tc<4, false><<<148, 256, GSMEM_BYTES>>>(Wl[1], ASl[1], ADl[1], x, W_in, b_in);
    k_attnagg<4><<<AGG_BLOCKS, EB>>>(1);
    k_bncoef<<<1, 128>>>(1, Gl[1], Bl[1]);
    // layer 2
    k_gemm_tc<1, false><<<148, 256, GSMEM_BYTES>>>(Wl[2], ASl[2], ADl[2], x, W_in, b_in);
    k_attnagg<1><<<AGG_BLOCKS, EB>>>(2);
    k_bncoef<<<1, 128>>>(2, Gl[2], Bl[2]);
    // MLP head (BN of layer 2 fused, no relu on BN)
    k_mlp1<<<1024, 64>>>(Wc1, bc1);
    k_mlp2<<<NN * 32 / EB, EB>>>(Wc2, bc2, out);
}